// round 3
// baseline (speedup 1.0000x reference)
#include <cuda_runtime.h>
#include <math.h>

#define BB 8
#define SS 1024
#define DMM 512
#define HH 8
#define DKK 32
#define DHH 64
#define NTOK (BB*SS)   /* 8192 */

// ---------------- device scratch (no allocations allowed) ----------------
__device__ float g_q [NTOK*256];   // [token][h*32+k]  (l2-normalized in place)
__device__ float g_k [NTOK*256];
__device__ float g_v [NTOK*512];   // [token][h*64+c]
__device__ float g_y [NTOK*512];   // attention out, concat layout
__device__ float g_t1[NTOK*512];   // attn projection out
__device__ float g_z1[NTOK*512];   // LN1 out
__device__ float g_t2[NTOK*512];   // FFN out

// ---------------- generic fp32 GEMM: C[M,N] = A[M,K] * W[N,K]^T (+bias, act) ----
// 64x64 tile, 256 threads, 4x4 micro-tile, k-chunk 16.
__global__ __launch_bounds__(256) void gemm_nt(
    const float* __restrict__ A, const float* __restrict__ W,
    const float* __restrict__ bias, float* __restrict__ C,
    int M, int N, int K, int act)
{
    __shared__ float As[16*64];
    __shared__ float Ws[16*64];
    const int tid = threadIdx.x;
    const int m0 = blockIdx.y * 64, n0 = blockIdx.x * 64;
    const int tr = tid >> 4, tc = tid & 15;
    const int r0 = tr * 4, c0 = tc * 4;
    const int lrow = tid >> 2;
    const int lk   = (tid & 3) * 4;

    float acc[4][4];
#pragma unroll
    for (int i = 0; i < 4; i++)
#pragma unroll
        for (int j = 0; j < 4; j++) acc[i][j] = 0.f;

    for (int k0 = 0; k0 < K; k0 += 16) {
        float4 av = *(const float4*)&A[(size_t)(m0 + lrow) * K + k0 + lk];
        float4 wv = *(const float4*)&W[(size_t)(n0 + lrow) * K + k0 + lk];
        __syncthreads();
        As[(lk+0)*64 + lrow] = av.x; As[(lk+1)*64 + lrow] = av.y;
        As[(lk+2)*64 + lrow] = av.z; As[(lk+3)*64 + lrow] = av.w;
        Ws[(lk+0)*64 + lrow] = wv.x; Ws[(lk+1)*64 + lrow] = wv.y;
        Ws[(lk+2)*64 + lrow] = wv.z; Ws[(lk+3)*64 + lrow] = wv.w;
        __syncthreads();
#pragma unroll
        for (int kk = 0; kk < 16; kk++) {
            float4 a4 = *(const float4*)&As[kk*64 + r0];
            float4 w4 = *(const float4*)&Ws[kk*64 + c0];
            acc[0][0] += a4.x*w4.x; acc[0][1] += a4.x*w4.y; acc[0][2] += a4.x*w4.z; acc[0][3] += a4.x*w4.w;
            acc[1][0] += a4.y*w4.x; acc[1][1] += a4.y*w4.y; acc[1][2] += a4.y*w4.z; acc[1][3] += a4.y*w4.w;
            acc[2][0] += a4.z*w4.x; acc[2][1] += a4.z*w4.y; acc[2][2] += a4.z*w4.z; acc[2][3] += a4.z*w4.w;
            acc[3][0] += a4.w*w4.x; acc[3][1] += a4.w*w4.y; acc[3][2] += a4.w*w4.z; acc[3][3] += a4.w*w4.w;
        }
    }

    float b4x = 0.f, b4y = 0.f, b4z = 0.f, b4w = 0.f;
    if (bias) {
        b4x = bias[n0+c0+0]; b4y = bias[n0+c0+1];
        b4z = bias[n0+c0+2]; b4w = bias[n0+c0+3];
    }
#pragma unroll
    for (int i = 0; i < 4; i++) {
        float4 o;
        o.x = acc[i][0] + b4x; o.y = acc[i][1] + b4y;
        o.z = acc[i][2] + b4z; o.w = acc[i][3] + b4w;
        if (act) {  // leaky relu, slope 0.01
            o.x = o.x > 0.f ? o.x : 0.01f * o.x;
            o.y = o.y > 0.f ? o.y : 0.01f * o.y;
            o.z = o.z > 0.f ? o.z : 0.01f * o.z;
            o.w = o.w > 0.f ? o.w : 0.01f * o.w;
        }
        *(float4*)&C[(size_t)(m0 + r0 + i) * N + n0 + c0] = o;
    }
}

// ---------------- l2 normalize 32-wide rows of g_q and g_k ----------------
__global__ __launch_bounds__(256) void l2norm_kernel(float* __restrict__ q, float* __restrict__ k)
{
    int gid  = blockIdx.x * blockDim.x + threadIdx.x;
    int gw   = gid >> 5;
    int lane = gid & 31;
    const int nrows = NTOK * HH;           // 65536 rows per tensor
    float* base = (gw < nrows) ? q : k;
    int row = gw % nrows;
    float v = base[(size_t)row * 32 + lane];
    float s = v * v;
#pragma unroll
    for (int o = 16; o > 0; o >>= 1) s += __shfl_xor_sync(0xffffffffu, s, o);
    float n = sqrtf(s);
    float d = fmaxf(n, 1e-12f);
    base[(size_t)row * 32 + lane] = v / d;
}

// ---------------- fused attention: scores + bias + mask + custom softmax + AV ----
// grid: (h, q_tile, b); block 256 threads; 64x64 tiles, 4x4 micro-tiles.
#define ATT_SMEM_FLOATS (32*68 + 32*68 + 64*68 + 64*68)
__global__ __launch_bounds__(256) void attn_kernel(
    const float* __restrict__ qn, const float* __restrict__ kn,
    const float* __restrict__ vfull, const float* __restrict__ dist,
    const float* __restrict__ omega, float* __restrict__ yout)
{
    extern __shared__ float sm[];
    float* qs = sm;                 // [32][68] transposed: qs[k*68 + r]
    float* ks = sm + 32*68;         // [32][68]
    float* vs = sm + 64*68;         // [64][68]: vs[t*68 + c]
    float* zs = sm + 128*68;        // [64][68]: zs[r*68 + t]

    const int h  = blockIdx.x;
    const int qi = blockIdx.y;
    const int b  = blockIdx.z;
    const int q0 = qi * 64;
    const int tid = threadIdx.x;
    const int tr = tid >> 4, tc = tid & 15;
    const int r0 = tr * 4, c0 = tc * 4;
    const float om = omega[h];

    // load q tile transposed
    {
        int r  = tid >> 2;
        int kq = (tid & 3) * 8;
        const float* src = qn + (size_t)(b*SS + q0 + r) * 256 + h*DKK + kq;
        float4 a = *(const float4*)src;
        float4 bq = *(const float4*)(src + 4);
        qs[(kq+0)*68 + r] = a.x;  qs[(kq+1)*68 + r] = a.y;
        qs[(kq+2)*68 + r] = a.z;  qs[(kq+3)*68 + r] = a.w;
        qs[(kq+4)*68 + r] = bq.x; qs[(kq+5)*68 + r] = bq.y;
        qs[(kq+6)*68 + r] = bq.z; qs[(kq+7)*68 + r] = bq.w;
    }

    float yacc[4][4];
    float rsl[4] = {0.f, 0.f, 0.f, 0.f};
#pragma unroll
    for (int i = 0; i < 4; i++)
#pragma unroll
        for (int j = 0; j < 4; j++) yacc[i][j] = 0.f;

    for (int kt = 0; kt <= qi; kt++) {
        const int t0 = kt * 64;
        __syncthreads();   // previous AV done before overwriting ks/vs/zs
        {
            int r  = tid >> 2;
            int kq = (tid & 3) * 8;
            const float* srcK = kn + (size_t)(b*SS + t0 + r) * 256 + h*DKK + kq;
            float4 a = *(const float4*)srcK;
            float4 bk = *(const float4*)(srcK + 4);
            ks[(kq+0)*68 + r] = a.x;  ks[(kq+1)*68 + r] = a.y;
            ks[(kq+2)*68 + r] = a.z;  ks[(kq+3)*68 + r] = a.w;
            ks[(kq+4)*68 + r] = bk.x; ks[(kq+5)*68 + r] = bk.y;
            ks[(kq+6)*68 + r] = bk.z; ks[(kq+7)*68 + r] = bk.w;

            int cq = (tid & 3) * 16;
            const float* srcV = vfull + (size_t)(b*SS + t0 + r) * 512 + h*DHH + cq;
#pragma unroll
            for (int i = 0; i < 4; i++) {
                float4 v4 = *(const float4*)(srcV + 4*i);
                *(float4*)(vs + r*68 + cq + 4*i) = v4;
            }
        }
        __syncthreads();

        // ---- scores: 4x4 micro-tile, dot over DK=32 ----
        float sacc[4][4];
#pragma unroll
        for (int i = 0; i < 4; i++)
#pragma unroll
            for (int j = 0; j < 4; j++) sacc[i][j] = 0.f;
#pragma unroll 4
        for (int k = 0; k < 32; k++) {
            float4 qv = *(const float4*)(qs + k*68 + r0);
            float4 kv = *(const float4*)(ks + k*68 + c0);
            sacc[0][0] += qv.x*kv.x; sacc[0][1] += qv.x*kv.y; sacc[0][2] += qv.x*kv.z; sacc[0][3] += qv.x*kv.w;
            sacc[1][0] += qv.y*kv.x; sacc[1][1] += qv.y*kv.y; sacc[1][2] += qv.y*kv.z; sacc[1][3] += qv.y*kv.w;
            sacc[2][0] += qv.z*kv.x; sacc[2][1] += qv.z*kv.y; sacc[2][2] += qv.z*kv.z; sacc[2][3] += qv.z*kv.w;
            sacc[3][0] += qv.w*kv.x; sacc[3][1] += qv.w*kv.y; sacc[3][2] += qv.w*kv.z; sacc[3][3] += qv.w*kv.w;
        }

        const int tbase = t0 + c0;
        const bool diag = (kt == qi);
#pragma unroll
        for (int i = 0; i < 4; i++) {
            const int qrow = q0 + r0 + i;
            float4 d4 = *(const float4*)(dist + (size_t)(b*SS + qrow) * SS + tbase);
            float z0 = __expf(sacc[i][0] + __expf(-om * d4.x) - 1.f);
            float z1 = __expf(sacc[i][1] + __expf(-om * d4.y) - 1.f);
            float z2 = __expf(sacc[i][2] + __expf(-om * d4.z) - 1.f);
            float z3 = __expf(sacc[i][3] + __expf(-om * d4.w) - 1.f);
            if (diag) {
                if (tbase + 0 > qrow) z0 = 0.f;
                if (tbase + 1 > qrow) z1 = 0.f;
                if (tbase + 2 > qrow) z2 = 0.f;
                if (tbase + 3 > qrow) z3 = 0.f;
            }
            rsl[i] += z0 + z1 + z2 + z3;
            *(float4*)(zs + (r0+i)*68 + c0) = make_float4(z0, z1, z2, z3);
        }
        __syncthreads();

        // ---- AV accumulate: y[r][c] += sum_t z[r][t] * v[t][c] ----
#pragma unroll 8
        for (int t = 0; t < 64; t++) {
            float4 v4 = *(const float4*)(vs + t*68 + c0);
#pragma unroll
            for (int i = 0; i < 4; i++) {
                float z = zs[(r0+i)*68 + t];
                yacc[i][0] += z * v4.x;
                yacc[i][1] += z * v4.y;
                yacc[i][2] += z * v4.z;
                yacc[i][3] += z * v4.w;
            }
        }
    }

    // reduce row-sums across the 16 lanes that share a row group (xor<16 stays in group)
#pragma unroll
    for (int i = 0; i < 4; i++) {
#pragma unroll
        for (int o = 8; o > 0; o >>= 1)
            rsl[i] += __shfl_xor_sync(0xffffffffu, rsl[i], o);
    }
#pragma unroll
    for (int i = 0; i < 4; i++) {
        float inv = 1.f / (rsl[i] + 1.f);
        float4 o;
        o.x = yacc[i][0] * inv; o.y = yacc[i][1] * inv;
        o.z = yacc[i][2] * inv; o.w = yacc[i][3] * inv;
        *(float4*)(yout + (size_t)(b*SS + q0 + r0 + i) * 512 + h*DHH + c0) = o;
    }
}

// ---------------- residual add + LayerNorm over 512, one block per token ----------
__global__ __launch_bounds__(128) void add_ln_kernel(
    const float* __restrict__ A, const float* __restrict__ Bs,
    const float* __restrict__ w, const float* __restrict__ bias,
    float* __restrict__ out)
{
    const int row = blockIdx.x;
    const int t = threadIdx.x;
    __shared__ float red[8];

    float4 a4 = *(const float4*)(A  + (size_t)row * 512 + t * 4);
    float4 b4 = *(const float4*)(Bs + (size_t)row * 512 + t * 4);
    float v0 = a4.x + b4.x, v1 = a4.y + b4.y, v2 = a4.z + b4.z, v3 = a4.w + b4.w;

    float s = v0 + v1 + v2 + v3;
#pragma unroll
    for (int o = 16; o > 0; o >>= 1) s += __shfl_xor_sync(0xffffffffu, s, o);
    int wid = t >> 5, lane = t & 31;
    if (!lane) red[wid] = s;
    __syncthreads();
    float mean = (red[0] + red[1] + red[2] + red[3]) * (1.f / 512.f);

    float d0 = v0 - mean, d1 = v1 - mean, d2 = v2 - mean, d3 = v3 - mean;
    float sv = d0*d0 + d1*d1 + d2*d2 + d3*d3;
#pragma unroll
    for (int o = 16; o > 0; o >>= 1) sv += __shfl_xor_sync(0xffffffffu, sv, o);
    if (!lane) red[4 + wid] = sv;
    __syncthreads();
    float var = (red[4] + red[5] + red[6] + red[7]) * (1.f / 512.f);
    float rstd = rsqrtf(var + 1e-5f);

    float4 w4  = *(const float4*)(w    + t * 4);
    float4 bb4 = *(const float4*)(bias + t * 4);
    float4 o4;
    o4.x = d0 * rstd * w4.x + bb4.x;
    o4.y = d1 * rstd * w4.y + bb4.y;
    o4.z = d2 * rstd * w4.z + bb4.z;
    o4.w = d3 * rstd * w4.w + bb4.w;
    *(float4*)(out + (size_t)row * 512 + t * 4) = o4;
}

// ---------------- launch ----------------
extern "C" void kernel_launch(void* const* d_in, const int* in_sizes, int n_in,
                              void* d_out, int out_size)
{
    const float* x     = (const float*)d_in[0];
    // d_in[1] = attn_mask (causal triu k=1) — recomputed from indices, not read
    const float* dist  = (const float*)d_in[2];
    const float* Wq    = (const float*)d_in[3];   // [H*DK, DM] = [256,512]
    const float* Wk    = (const float*)d_in[4];
    const float* Wv    = (const float*)d_in[5];   // [H*DH, DM] = [512,512]
    const float* omega = (const float*)d_in[6];
    const float* Wo    = (const float*)d_in[7];   // [512,512]
    const float* bo    = (const float*)d_in[8];
    const float* Wf    = (const float*)d_in[9];   // [512,512]
    const float* bf    = (const float*)d_in[10];
    const float* l1w   = (const float*)d_in[11];
    const float* l1b   = (const float*)d_in[12];
    const float* l2w   = (const float*)d_in[13];
    const float* l2b   = (const float*)d_in[14];
    float* out = (float*)d_out;

    float *gq, *gk, *gv, *gy, *gt1, *gz1, *gt2;
    cudaGetSymbolAddress((void**)&gq,  g_q);
    cudaGetSymbolAddress((void**)&gk,  g_k);
    cudaGetSymbolAddress((void**)&gv,  g_v);
    cudaGetSymbolAddress((void**)&gy,  g_y);
    cudaGetSymbolAddress((void**)&gt1, g_t1);
    cudaGetSymbolAddress((void**)&gz1, g_z1);
    cudaGetSymbolAddress((void**)&gt2, g_t2);

    const int ATT_SMEM_BYTES = ATT_SMEM_FLOATS * sizeof(float);   // 52224
    cudaFuncSetAttribute(attn_kernel, cudaFuncAttributeMaxDynamicSharedMemorySize,
                         ATT_SMEM_BYTES);

    // QKV projections
    gemm_nt<<<dim3(4, 128), 256>>>(x, Wq, nullptr, gq, NTOK, 256, 512, 0);
    gemm_nt<<<dim3(4, 128), 256>>>(x, Wk, nullptr, gk, NTOK, 256, 512, 0);
    gemm_nt<<<dim3(8, 128), 256>>>(x, Wv, nullptr, gv, NTOK, 512, 512, 0);

    // l2 normalize q and k (32-wide per head)
    l2norm_kernel<<<2 * NTOK * HH * 32 / 256, 256>>>(gq, gk);

    // fused attention -> concat layout
    attn_kernel<<<dim3(HH, SS / 64, BB), 256, ATT_SMEM_BYTES>>>(gq, gk, gv, dist, omega, gy);

    // output projection + LN1
    gemm_nt<<<dim3(8, 128), 256>>>(gy, Wo, bo, gt1, NTOK, 512, 512, 0);
    add_ln_kernel<<<NTOK, 128>>>(x, gt1, l1w, l1b, gz1);

    // FFN + leaky relu + LN2
    gemm_nt<<<dim3(8, 128), 256>>>(gz1, Wf, bf, gt2, NTOK, 512, 512, 1);
    add_ln_kernel<<<NTOK, 128>>>(gz1, gt2, l2w, l2b, out);
}

// round 4
// speedup vs baseline: 2.0504x; 2.0504x over previous
#include <cuda_runtime.h>
#include <math.h>

#define BB 8
#define SS 1024
#define DMM 512
#define HH 8
#define DKK 32
#define DHH 64
#define NTOK (BB*SS)   /* 8192 */

// ---------------- device scratch ----------------
__device__ float g_q [NTOK*256];   // [token][h*32+k] raw projections (normalized on the fly)
__device__ float g_k [NTOK*256];
__device__ float g_v [NTOK*512];   // [token][h*64+c]
__device__ float g_y [NTOK*512];   // attention out, concat layout
__device__ float g_t1[NTOK*512];
__device__ float g_z1[NTOK*512];
__device__ float g_t2[NTOK*512];

// ---------------- tf32 helpers ----------------
__device__ __forceinline__ unsigned f2t(float f) {
    unsigned u; asm("cvt.rna.tf32.f32 %0, %1;" : "=r"(u) : "f"(f)); return u;
}
__device__ __forceinline__ void mma8(float* c, const unsigned* a, const unsigned* b) {
    asm volatile(
        "mma.sync.aligned.m16n8k8.row.col.f32.tf32.tf32.f32 "
        "{%0,%1,%2,%3},{%4,%5,%6,%7},{%8,%9},{%0,%1,%2,%3};"
        : "+f"(c[0]), "+f"(c[1]), "+f"(c[2]), "+f"(c[3])
        : "r"(a[0]), "r"(a[1]), "r"(a[2]), "r"(a[3]), "r"(b[0]), "r"(b[1]));
}

// ---------------- tf32 GEMM: C[M,N] = A[M,K] * W[N,K]^T (+bias, leaky) ----------
// CTA tile 128x64, 8 warps (4x2), warp tile 32x32 (2 m16 x 4 n8), k-chunk 16.
__global__ __launch_bounds__(256) void gemm_tf32(
    const float* __restrict__ A, const float* __restrict__ W,
    const float* __restrict__ bias, float* __restrict__ C,
    int M, int N, int K, int act)
{
    __shared__ unsigned As[128 * 20];   // [row][k] stride 20 (conflict-free frags)
    __shared__ unsigned Ws[64 * 20];    // [n][k]  stride 20

    const int tid  = threadIdx.x;
    const int warp = tid >> 5, lane = tid & 31;
    const int g = lane >> 2, c = lane & 3;
    const int warpM = (warp >> 1) * 32, warpN = (warp & 1) * 32;
    const int m0 = blockIdx.y * 128, n0 = blockIdx.x * 64;

    const int arow = tid >> 1, akq = (tid & 1) * 8;
    const int wrow = tid >> 2, wkq = (tid & 3) * 4;

    float acc[2][4][4];
#pragma unroll
    for (int mi = 0; mi < 2; mi++)
#pragma unroll
        for (int ni = 0; ni < 4; ni++)
#pragma unroll
            for (int j = 0; j < 4; j++) acc[mi][ni][j] = 0.f;

    for (int k0 = 0; k0 < K; k0 += 16) {
        float4 a1 = *(const float4*)&A[(size_t)(m0 + arow) * K + k0 + akq];
        float4 a2 = *(const float4*)&A[(size_t)(m0 + arow) * K + k0 + akq + 4];
        float4 wv = *(const float4*)&W[(size_t)(n0 + wrow) * K + k0 + wkq];
        __syncthreads();
        unsigned* ap = &As[arow * 20 + akq];
        ap[0] = f2t(a1.x); ap[1] = f2t(a1.y); ap[2] = f2t(a1.z); ap[3] = f2t(a1.w);
        ap[4] = f2t(a2.x); ap[5] = f2t(a2.y); ap[6] = f2t(a2.z); ap[7] = f2t(a2.w);
        unsigned* wp = &Ws[wrow * 20 + wkq];
        wp[0] = f2t(wv.x); wp[1] = f2t(wv.y); wp[2] = f2t(wv.z); wp[3] = f2t(wv.w);
        __syncthreads();

#pragma unroll
        for (int kk = 0; kk < 16; kk += 8) {
            unsigned af[2][4];
#pragma unroll
            for (int mi = 0; mi < 2; mi++) {
                int base = (warpM + mi * 16 + g) * 20 + kk + c;
                af[mi][0] = As[base];
                af[mi][1] = As[base + 8 * 20];
                af[mi][2] = As[base + 4];
                af[mi][3] = As[base + 8 * 20 + 4];
            }
            unsigned bf[4][2];
#pragma unroll
            for (int ni = 0; ni < 4; ni++) {
                int bb = (warpN + ni * 8 + g) * 20 + kk + c;
                bf[ni][0] = Ws[bb];
                bf[ni][1] = Ws[bb + 4];
            }
#pragma unroll
            for (int mi = 0; mi < 2; mi++)
#pragma unroll
                for (int ni = 0; ni < 4; ni++)
                    mma8(acc[mi][ni], af[mi], bf[ni]);
        }
    }

#pragma unroll
    for (int mi = 0; mi < 2; mi++) {
        int row0 = m0 + warpM + mi * 16 + g;
#pragma unroll
        for (int ni = 0; ni < 4; ni++) {
            int col = n0 + warpN + ni * 8 + 2 * c;
            float bx = bias ? bias[col] : 0.f;
            float by = bias ? bias[col + 1] : 0.f;
            float o0 = acc[mi][ni][0] + bx, o1 = acc[mi][ni][1] + by;
            float o2 = acc[mi][ni][2] + bx, o3 = acc[mi][ni][3] + by;
            if (act) {
                o0 = o0 > 0.f ? o0 : 0.01f * o0;
                o1 = o1 > 0.f ? o1 : 0.01f * o1;
                o2 = o2 > 0.f ? o2 : 0.01f * o2;
                o3 = o3 > 0.f ? o3 : 0.01f * o3;
            }
            *(float2*)&C[(size_t)row0 * N + col]       = make_float2(o0, o1);
            *(float2*)&C[(size_t)(row0 + 8) * N + col] = make_float2(o2, o3);
        }
    }
}

// ---------------- fused attention, all matmuls on mma.tf32 ----------------
// grid (h, q_tile, b); 256 threads = 8 warps in 4(m)x2(n); CTA tile 64(q) x 64(t / DH).
#define QK_ST 36
#define V_ST  72
#define Z_ST  68
#define ATT_SMEM_BYTES ((64*QK_ST*2 + 64*V_ST + 64*Z_ST + 64) * 4)

__global__ __launch_bounds__(256) void attn_kernel(
    const float* __restrict__ qn, const float* __restrict__ kn,
    const float* __restrict__ vfull, const float* __restrict__ dist,
    const float* __restrict__ omega, float* __restrict__ yout)
{
    extern __shared__ unsigned smx[];
    unsigned* qs  = smx;                    // [64][36] tf32, l2-normalized
    unsigned* ks  = qs + 64 * QK_ST;        // [64][36]
    unsigned* vs  = ks + 64 * QK_ST;        // [64][72]
    unsigned* zsm = vs + 64 * V_ST;         // [64][68] z in tf32
    float*    rs  = (float*)(zsm + 64 * Z_ST);  // [64] row sums

    const int h  = blockIdx.x;
    const int qi = blockIdx.y;
    const int b  = blockIdx.z;
    const int q0 = qi * 64;
    const int tid  = threadIdx.x;
    const int warp = tid >> 5, lane = tid & 31;
    const int g = lane >> 2, c = lane & 3;
    const int warpM = (warp >> 1) * 16;     // 4 m-warps x 16 rows
    const int warpN = (warp & 1) * 32;      // 2 n-warps x 32 cols
    const float om = omega[h];

    if (tid < 64) rs[tid] = 0.f;

    const int lrow = tid >> 2, lkq = (tid & 3) * 8, lcq = (tid & 3) * 16;

    // ---- load Q tile, l2-normalize per row, convert to tf32 ----
    {
        const float* qp = qn + (size_t)(b * SS + q0 + lrow) * 256 + h * DKK + lkq;
        float4 a = *(const float4*)qp;
        float4 d = *(const float4*)(qp + 4);
        float ssq = a.x*a.x + a.y*a.y + a.z*a.z + a.w*a.w
                  + d.x*d.x + d.y*d.y + d.z*d.z + d.w*d.w;
        ssq += __shfl_xor_sync(0xffffffffu, ssq, 1);
        ssq += __shfl_xor_sync(0xffffffffu, ssq, 2);
        float scl = 1.f / fmaxf(sqrtf(ssq), 1e-12f);
        unsigned* qd = &qs[lrow * QK_ST + lkq];
        qd[0] = f2t(a.x*scl); qd[1] = f2t(a.y*scl); qd[2] = f2t(a.z*scl); qd[3] = f2t(a.w*scl);
        qd[4] = f2t(d.x*scl); qd[5] = f2t(d.y*scl); qd[6] = f2t(d.z*scl); qd[7] = f2t(d.w*scl);
    }
    __syncthreads();

    float oacc[4][4];
#pragma unroll
    for (int ni = 0; ni < 4; ni++)
#pragma unroll
        for (int j = 0; j < 4; j++) oacc[ni][j] = 0.f;

    for (int kt = 0; kt <= qi; kt++) {
        const int t0 = kt * 64;
        // ---- load K (normalize) and V tiles ----
        {
            const float* kp = kn + (size_t)(b * SS + t0 + lrow) * 256 + h * DKK + lkq;
            float4 a = *(const float4*)kp;
            float4 d = *(const float4*)(kp + 4);
            float ssq = a.x*a.x + a.y*a.y + a.z*a.z + a.w*a.w
                      + d.x*d.x + d.y*d.y + d.z*d.z + d.w*d.w;
            ssq += __shfl_xor_sync(0xffffffffu, ssq, 1);
            ssq += __shfl_xor_sync(0xffffffffu, ssq, 2);
            float scl = 1.f / fmaxf(sqrtf(ssq), 1e-12f);
            unsigned* kd = &ks[lrow * QK_ST + lkq];
            kd[0] = f2t(a.x*scl); kd[1] = f2t(a.y*scl); kd[2] = f2t(a.z*scl); kd[3] = f2t(a.w*scl);
            kd[4] = f2t(d.x*scl); kd[5] = f2t(d.y*scl); kd[6] = f2t(d.z*scl); kd[7] = f2t(d.w*scl);

            const float* vp = vfull + (size_t)(b * SS + t0 + lrow) * 512 + h * DHH + lcq;
#pragma unroll
            for (int i = 0; i < 4; i++) {
                float4 v4 = *(const float4*)(vp + 4 * i);
                unsigned* vd = &vs[lrow * V_ST + lcq + 4 * i];
                vd[0] = f2t(v4.x); vd[1] = f2t(v4.y); vd[2] = f2t(v4.z); vd[3] = f2t(v4.w);
            }
        }
        __syncthreads();

        // ---- S = Q * K^T (m16 x 4n8 per warp, K=32 = 4 k8 steps) ----
        float sfr[4][4];
#pragma unroll
        for (int ni = 0; ni < 4; ni++)
#pragma unroll
            for (int j = 0; j < 4; j++) sfr[ni][j] = 0.f;
#pragma unroll
        for (int kk = 0; kk < 32; kk += 8) {
            unsigned af[4];
            int base = (warpM + g) * QK_ST + kk + c;
            af[0] = qs[base];
            af[1] = qs[base + 8 * QK_ST];
            af[2] = qs[base + 4];
            af[3] = qs[base + 8 * QK_ST + 4];
#pragma unroll
            for (int ni = 0; ni < 4; ni++) {
                int bb = (warpN + ni * 8 + g) * QK_ST + kk + c;
                unsigned bf[2] = { ks[bb], ks[bb + 4] };
                mma8(sfr[ni], af, bf);
            }
        }

        // ---- epilogue: distance bias + exp + causal mask; z -> smem (tf32) ----
        const bool diag = (kt == qi);
        const int qrow0 = q0 + warpM + g, qrow1 = qrow0 + 8;
        float rsum0 = 0.f, rsum1 = 0.f;
#pragma unroll
        for (int ni = 0; ni < 4; ni++) {
            int tc0 = t0 + warpN + ni * 8 + 2 * c;
            float2 d0 = *(const float2*)(dist + (size_t)(b * SS + qrow0) * SS + tc0);
            float2 d1 = *(const float2*)(dist + (size_t)(b * SS + qrow1) * SS + tc0);
            float z00 = __expf(sfr[ni][0] + __expf(-om * d0.x) - 1.f);
            float z01 = __expf(sfr[ni][1] + __expf(-om * d0.y) - 1.f);
            float z10 = __expf(sfr[ni][2] + __expf(-om * d1.x) - 1.f);
            float z11 = __expf(sfr[ni][3] + __expf(-om * d1.y) - 1.f);
            if (diag) {
                if (tc0     > qrow0) z00 = 0.f;
                if (tc0 + 1 > qrow0) z01 = 0.f;
                if (tc0     > qrow1) z10 = 0.f;
                if (tc0 + 1 > qrow1) z11 = 0.f;
            }
            rsum0 += z00 + z01;
            rsum1 += z10 + z11;
            int zc = warpN + ni * 8 + 2 * c;
            unsigned* zp0 = &zsm[(warpM + g) * Z_ST + zc];
            zp0[0] = f2t(z00); zp0[1] = f2t(z01);
            unsigned* zp1 = &zsm[(warpM + g + 8) * Z_ST + zc];
            zp1[0] = f2t(z10); zp1[1] = f2t(z11);
        }
        rsum0 += __shfl_xor_sync(0xffffffffu, rsum0, 1);
        rsum0 += __shfl_xor_sync(0xffffffffu, rsum0, 2);
        rsum1 += __shfl_xor_sync(0xffffffffu, rsum1, 1);
        rsum1 += __shfl_xor_sync(0xffffffffu, rsum1, 2);
        if (c == 0) {
            atomicAdd(&rs[warpM + g], rsum0);
            atomicAdd(&rs[warpM + g + 8], rsum1);
        }
        __syncthreads();   // z + v visible to all before AV

        // ---- O += Z * V (K=64 = 8 k8 steps) ----
#pragma unroll
        for (int kk = 0; kk < 64; kk += 8) {
            unsigned af[4];
            int base = (warpM + g) * Z_ST + kk + c;
            af[0] = zsm[base];
            af[1] = zsm[base + 8 * Z_ST];
            af[2] = zsm[base + 4];
            af[3] = zsm[base + 8 * Z_ST + 4];
#pragma unroll
            for (int ni = 0; ni < 4; ni++) {
                int bb = (kk + c) * V_ST + warpN + ni * 8 + g;
                unsigned bf[2] = { vs[bb], vs[bb + 4 * V_ST] };
                mma8(oacc[ni], af, bf);
            }
        }
        __syncthreads();   // AV done before next tile overwrites ks/vs/zsm
    }

    // ---- normalize by (rowsum + 1) and write concat layout ----
    float inv0 = 1.f / (rs[warpM + g] + 1.f);
    float inv1 = 1.f / (rs[warpM + g + 8] + 1.f);
#pragma unroll
    for (int ni = 0; ni < 4; ni++) {
        int col = h * DHH + warpN + ni * 8 + 2 * c;
        float* op0 = yout + (size_t)(b * SS + q0 + warpM + g) * 512 + col;
        float* op1 = yout + (size_t)(b * SS + q0 + warpM + g + 8) * 512 + col;
        *(float2*)op0 = make_float2(oacc[ni][0] * inv0, oacc[ni][1] * inv0);
        *(float2*)op1 = make_float2(oacc[ni][2] * inv1, oacc[ni][3] * inv1);
    }
}

// ---------------- residual add + LayerNorm over 512 ----------------
__global__ __launch_bounds__(128) void add_ln_kernel(
    const float* __restrict__ A, const float* __restrict__ Bs,
    const float* __restrict__ w, const float* __restrict__ bias,
    float* __restrict__ out)
{
    const int row = blockIdx.x;
    const int t = threadIdx.x;
    __shared__ float red[8];

    float4 a4 = *(const float4*)(A  + (size_t)row * 512 + t * 4);
    float4 b4 = *(const float4*)(Bs + (size_t)row * 512 + t * 4);
    float v0 = a4.x + b4.x, v1 = a4.y + b4.y, v2 = a4.z + b4.z, v3 = a4.w + b4.w;

    float s = v0 + v1 + v2 + v3;
#pragma unroll
    for (int o = 16; o > 0; o >>= 1) s += __shfl_xor_sync(0xffffffffu, s, o);
    int wid = t >> 5, lane = t & 31;
    if (!lane) red[wid] = s;
    __syncthreads();
    float mean = (red[0] + red[1] + red[2] + red[3]) * (1.f / 512.f);

    float d0 = v0 - mean, d1 = v1 - mean, d2 = v2 - mean, d3 = v3 - mean;
    float sv = d0*d0 + d1*d1 + d2*d2 + d3*d3;
#pragma unroll
    for (int o = 16; o > 0; o >>= 1) sv += __shfl_xor_sync(0xffffffffu, sv, o);
    if (!lane) red[4 + wid] = sv;
    __syncthreads();
    float var = (red[4] + red[5] + red[6] + red[7]) * (1.f / 512.f);
    float rstd = rsqrtf(var + 1e-5f);

    float4 w4  = *(const float4*)(w    + t * 4);
    float4 bb4 = *(const float4*)(bias + t * 4);
    float4 o4;
    o4.x = d0 * rstd * w4.x + bb4.x;
    o4.y = d1 * rstd * w4.y + bb4.y;
    o4.z = d2 * rstd * w4.z + bb4.z;
    o4.w = d3 * rstd * w4.w + bb4.w;
    *(float4*)(out + (size_t)row * 512 + t * 4) = o4;
}

// ---------------- launch ----------------
extern "C" void kernel_launch(void* const* d_in, const int* in_sizes, int n_in,
                              void* d_out, int out_size)
{
    const float* x     = (const float*)d_in[0];
    const float* dist  = (const float*)d_in[2];
    const float* Wq    = (const float*)d_in[3];
    const float* Wk    = (const float*)d_in[4];
    const float* Wv    = (const float*)d_in[5];
    const float* omega = (const float*)d_in[6];
    const float* Wo    = (const float*)d_in[7];
    const float* bo    = (const float*)d_in[8];
    const float* Wf    = (const float*)d_in[9];
    const float* bf    = (const float*)d_in[10];
    const float* l1w   = (const float*)d_in[11];
    const float* l1b   = (const float*)d_in[12];
    const float* l2w   = (const float*)d_in[13];
    const float* l2b   = (const float*)d_in[14];
    float* out = (float*)d_out;

    float *gq, *gk, *gv, *gy, *gt1, *gz1, *gt2;
    cudaGetSymbolAddress((void**)&gq,  g_q);
    cudaGetSymbolAddress((void**)&gk,  g_k);
    cudaGetSymbolAddress((void**)&gv,  g_v);
    cudaGetSymbolAddress((void**)&gy,  g_y);
    cudaGetSymbolAddress((void**)&gt1, g_t1);
    cudaGetSymbolAddress((void**)&gz1, g_z1);
    cudaGetSymbolAddress((void**)&gt2, g_t2);

    cudaFuncSetAttribute(attn_kernel, cudaFuncAttributeMaxDynamicSharedMemorySize,
                         ATT_SMEM_BYTES);

    // QKV projections (tf32 tensor cores)
    gemm_tf32<<<dim3(4, 64), 256>>>(x, Wq, nullptr, gq, NTOK, 256, 512, 0);
    gemm_tf32<<<dim3(4, 64), 256>>>(x, Wk, nullptr, gk, NTOK, 256, 512, 0);
    gemm_tf32<<<dim3(8, 64), 256>>>(x, Wv, nullptr, gv, NTOK, 512, 512, 0);

    // fused attention (l2norm fused into tile loads) -> concat layout
    attn_kernel<<<dim3(HH, SS / 64, BB), 256, ATT_SMEM_BYTES>>>(gq, gk, gv, dist, omega, gy);

    // output projection + LN1
    gemm_tf32<<<dim3(8, 64), 256>>>(gy, Wo, bo, gt1, NTOK, 512, 512, 0);
    add_ln_kernel<<<NTOK, 128>>>(x, gt1, l1w, l1b, gz1);

    // FFN + leaky relu + LN2
    gemm_tf32<<<dim3(8, 64), 256>>>(gz1, Wf, bf, gt2, NTOK, 512, 512, 1);
    add_ln_kernel<<<NTOK, 128>>>(gz1, gt2, l2w, l2b, out);
}

// round 5
// speedup vs baseline: 2.7341x; 1.3334x over previous
#include <cuda_runtime.h>
#include <math.h>

#define BB 8
#define SS 1024
#define HH 8
#define NTOK 8192

// ---------------- device scratch ----------------
__device__ float g_q [NTOK*256];   // [token][h*32+k], l2-normalized (GEMM epilogue)
__device__ float g_k [NTOK*256];
__device__ float g_v [NTOK*512];   // [token][h*64+c]
__device__ float g_y [NTOK*512];
__device__ float g_t1[NTOK*512];
__device__ float g_z1[NTOK*512];
__device__ float g_t2[NTOK*512];

// ---------------- primitives ----------------
__device__ __forceinline__ void mma8(float* c, const unsigned* a, const unsigned* b) {
    asm volatile(
        "mma.sync.aligned.m16n8k8.row.col.f32.tf32.tf32.f32 "
        "{%0,%1,%2,%3},{%4,%5,%6,%7},{%8,%9},{%0,%1,%2,%3};"
        : "+f"(c[0]), "+f"(c[1]), "+f"(c[2]), "+f"(c[3])
        : "r"(a[0]), "r"(a[1]), "r"(a[2]), "r"(a[3]), "r"(b[0]), "r"(b[1]));
}
__device__ __forceinline__ void cpa16(unsigned dst, const void* src) {
    asm volatile("cp.async.cg.shared.global [%0], [%1], 16;\n" :: "r"(dst), "l"(src));
}
#define CP_COMMIT asm volatile("cp.async.commit_group;\n" ::: "memory")
#define CP_WAIT0  asm volatile("cp.async.wait_group 0;\n" ::: "memory")

// ---------------- GEMM: C[M,N] = A[M,K] * W[N,K]^T ----------------
// CTA tile 128x128, 8 warps (4m x 2n), warp tile 32x64, 2-stage cp.async, k-chunk 16.
// QKV mode: blockIdx.x selects Wq/Wk/Wv target; q/k epilogue does per-head l2norm.
// Generic mode: bias + optional leaky relu.
template<bool QKV>
__global__ __launch_bounds__(256, 2) void gemm_k(
    const float* __restrict__ A, const float* __restrict__ W0,
    const float* __restrict__ W1, const float* __restrict__ W2,
    const float* __restrict__ bias,
    float* __restrict__ C0, float* __restrict__ C1, float* __restrict__ C2,
    int Ngen, int K, int act)
{
    __shared__ unsigned As[2][128*20];   // row stride 20 words (80B, 16B-aligned, conflict-free)
    __shared__ unsigned Ws[2][128*20];

    const int tid = threadIdx.x, warp = tid >> 5, lane = tid & 31;
    const int g = lane >> 2, c = lane & 3;
    const int warpM = (warp >> 1) * 32, warpN = (warp & 1) * 64;
    const int m0 = blockIdx.y * 128;
    const int bx = blockIdx.x;

    const float* W; float* C; int Nout, col0; bool norm = false;
    if (QKV) {
        if (bx < 2)      { W = W0; C = C0; Nout = 256; col0 = bx * 128;       norm = true; }
        else if (bx < 4) { W = W1; C = C1; Nout = 256; col0 = (bx - 2) * 128; norm = true; }
        else             { W = W2; C = C2; Nout = 512; col0 = (bx - 4) * 128; }
    } else { W = W0; C = C0; Nout = Ngen; col0 = bx * 128; }

    unsigned sA = (unsigned)__cvta_generic_to_shared(&As[0][0]);
    unsigned sW = (unsigned)__cvta_generic_to_shared(&Ws[0][0]);

    auto pre = [&](int kc, int st) {
        const int k0 = kc * 16;
#pragma unroll
        for (int i = 0; i < 2; i++) {
            int slot = tid + i * 256;          // 512 slots: 128 rows x 4 chunks of 16B
            int row = slot >> 2, ch = slot & 3;
            cpa16(sA + (unsigned)(st * 2560 + row * 20 + ch * 4) * 4,
                  A + (size_t)(m0 + row) * K + k0 + ch * 4);
            cpa16(sW + (unsigned)(st * 2560 + row * 20 + ch * 4) * 4,
                  W + (size_t)(col0 + row) * K + k0 + ch * 4);
        }
    };

    float acc[2][8][4];
#pragma unroll
    for (int mi = 0; mi < 2; mi++)
#pragma unroll
        for (int ni = 0; ni < 8; ni++)
#pragma unroll
            for (int j = 0; j < 4; j++) acc[mi][ni][j] = 0.f;

    const int NC = K / 16;
    pre(0, 0); CP_COMMIT;
    int st = 0;
    for (int kc = 0; kc < NC; kc++) {
        CP_WAIT0;
        __syncthreads();
        if (kc + 1 < NC) pre(kc + 1, st ^ 1);
        CP_COMMIT;

        const unsigned* as = &As[st][0];
        const unsigned* ws = &Ws[st][0];
#pragma unroll
        for (int kk = 0; kk < 16; kk += 8) {
            unsigned af[2][4];
#pragma unroll
            for (int mi = 0; mi < 2; mi++) {
                int ba = (warpM + mi * 16 + g) * 20 + kk + c;
                af[mi][0] = as[ba];       af[mi][1] = as[ba + 160];
                af[mi][2] = as[ba + 4];   af[mi][3] = as[ba + 164];
            }
#pragma unroll
            for (int ni = 0; ni < 8; ni++) {
                int bb = (warpN + ni * 8 + g) * 20 + kk + c;
                unsigned bf[2] = { ws[bb], ws[bb + 4] };
#pragma unroll
                for (int mi = 0; mi < 2; mi++) mma8(acc[mi][ni], af[mi], bf);
            }
        }
        st ^= 1;
    }

#pragma unroll
    for (int mi = 0; mi < 2; mi++) {
        float r0A = 1.f, r0B = 1.f, r1A = 1.f, r1B = 1.f;
        if (QKV && norm) {
            // per-head (32-col) l2 norms; warp n-span 64 = heads A (ni<4) and B (ni>=4)
            float a0 = 0.f, a1 = 0.f, b0 = 0.f, b1 = 0.f;
#pragma unroll
            for (int ni = 0; ni < 4; ni++) {
                a0 += acc[mi][ni][0]*acc[mi][ni][0] + acc[mi][ni][1]*acc[mi][ni][1];
                a1 += acc[mi][ni][2]*acc[mi][ni][2] + acc[mi][ni][3]*acc[mi][ni][3];
            }
#pragma unroll
            for (int ni = 4; ni < 8; ni++) {
                b0 += acc[mi][ni][0]*acc[mi][ni][0] + acc[mi][ni][1]*acc[mi][ni][1];
                b1 += acc[mi][ni][2]*acc[mi][ni][2] + acc[mi][ni][3]*acc[mi][ni][3];
            }
            a0 += __shfl_xor_sync(0xffffffffu, a0, 1); a0 += __shfl_xor_sync(0xffffffffu, a0, 2);
            a1 += __shfl_xor_sync(0xffffffffu, a1, 1); a1 += __shfl_xor_sync(0xffffffffu, a1, 2);
            b0 += __shfl_xor_sync(0xffffffffu, b0, 1); b0 += __shfl_xor_sync(0xffffffffu, b0, 2);
            b1 += __shfl_xor_sync(0xffffffffu, b1, 1); b1 += __shfl_xor_sync(0xffffffffu, b1, 2);
            r0A = 1.f / fmaxf(sqrtf(a0), 1e-12f);
            r1A = 1.f / fmaxf(sqrtf(a1), 1e-12f);
            r0B = 1.f / fmaxf(sqrtf(b0), 1e-12f);
            r1B = 1.f / fmaxf(sqrtf(b1), 1e-12f);
        }
        const int row0 = m0 + warpM + mi * 16 + g;
#pragma unroll
        for (int ni = 0; ni < 8; ni++) {
            const int col = col0 + warpN + ni * 8 + 2 * c;
            float o0 = acc[mi][ni][0], o1 = acc[mi][ni][1];
            float o2 = acc[mi][ni][2], o3 = acc[mi][ni][3];
            if (QKV) {
                if (norm) {
                    float ra = (ni < 4) ? r0A : r0B;
                    float rb = (ni < 4) ? r1A : r1B;
                    o0 *= ra; o1 *= ra; o2 *= rb; o3 *= rb;
                }
            } else {
                float bx_ = bias[col], by_ = bias[col + 1];
                o0 += bx_; o1 += by_; o2 += bx_; o3 += by_;
                if (act) {
                    o0 = o0 > 0.f ? o0 : 0.01f * o0;
                    o1 = o1 > 0.f ? o1 : 0.01f * o1;
                    o2 = o2 > 0.f ? o2 : 0.01f * o2;
                    o3 = o3 > 0.f ? o3 : 0.01f * o3;
                }
            }
            *(float2*)&C[(size_t)row0 * Nout + col]       = make_float2(o0, o1);
            *(float2*)&C[(size_t)(row0 + 8) * Nout + col] = make_float2(o2, o3);
        }
    }
}

// ---------------- fused attention, cp.async double-buffered, Q frags in regs ----
#define KST 36
#define VST 72
#define ZST 68
#define ATT_WORDS (64*KST + 2*64*KST + 2*64*VST + 64*ZST + 64)

__global__ __launch_bounds__(256) void attn2(
    const float* __restrict__ qn, const float* __restrict__ kn,
    const float* __restrict__ vf, const float* __restrict__ dist,
    const float* __restrict__ omega, float* __restrict__ yout)
{
    extern __shared__ unsigned sm[];
    unsigned* qs = sm;                          // [64][36]
    unsigned* ks = qs + 64 * KST;               // [2][64][36]
    unsigned* vs = ks + 2 * 64 * KST;           // [2][64][72]
    float*    zs = (float*)(vs + 2 * 64 * VST); // [64][68]
    float*    rs = zs + 64 * ZST;               // [64]

    const int h = blockIdx.x, qi = blockIdx.y, b = blockIdx.z, q0 = qi * 64;
    const int tid = threadIdx.x, warp = tid >> 5, lane = tid & 31;
    const int g = lane >> 2, c = lane & 3;
    const int warpM = (warp >> 1) * 16, warpN = (warp & 1) * 32;
    const float om = omega[h];
    if (tid < 64) rs[tid] = 0.f;

    const unsigned sq = (unsigned)__cvta_generic_to_shared(qs);
    const unsigned sk = (unsigned)__cvta_generic_to_shared(ks);
    const unsigned sv = (unsigned)__cvta_generic_to_shared(vs);

    auto ldK = [&](int st, int t0) {
#pragma unroll
        for (int i = 0; i < 2; i++) {
            int slot = tid + i * 256, row = slot >> 3, ch = slot & 7;
            cpa16(sk + (unsigned)(st * 64 * KST + row * KST + ch * 4) * 4,
                  kn + (size_t)(b * SS + t0 + row) * 256 + h * 32 + ch * 4);
        }
    };
    auto ldV = [&](int st, int t0) {
#pragma unroll
        for (int i = 0; i < 4; i++) {
            int slot = tid + i * 256, row = slot >> 4, ch = slot & 15;
            cpa16(sv + (unsigned)(st * 64 * VST + row * VST + ch * 4) * 4,
                  vf + (size_t)(b * SS + t0 + row) * 512 + h * 64 + ch * 4);
        }
    };
    // Q tile
#pragma unroll
    for (int i = 0; i < 2; i++) {
        int slot = tid + i * 256, row = slot >> 3, ch = slot & 7;
        cpa16(sq + (unsigned)(row * KST + ch * 4) * 4,
              qn + (size_t)(b * SS + q0 + row) * 256 + h * 32 + ch * 4);
    }
    ldK(0, 0); ldV(0, 0); CP_COMMIT;

    unsigned qf[4][4];
    float oacc[4][4];
#pragma unroll
    for (int ni = 0; ni < 4; ni++)
#pragma unroll
        for (int j = 0; j < 4; j++) oacc[ni][j] = 0.f;

    int st = 0;
    for (int kt = 0; kt <= qi; kt++) {
        const int t0 = kt * 64;
        CP_WAIT0;
        __syncthreads();
        if (kt == 0) {   // hoist Q fragments into registers (constant over kt loop)
#pragma unroll
            for (int kk = 0; kk < 4; kk++) {
                int ba = (warpM + g) * KST + kk * 8 + c;
                qf[kk][0] = qs[ba];           qf[kk][1] = qs[ba + 8 * KST];
                qf[kk][2] = qs[ba + 4];       qf[kk][3] = qs[ba + 8 * KST + 4];
            }
        }
        if (kt < qi) { ldK(st ^ 1, t0 + 64); ldV(st ^ 1, t0 + 64); }
        CP_COMMIT;

        const unsigned* kcur = ks + st * 64 * KST;
        const unsigned* vcur = vs + st * 64 * VST;

        // ---- S = Q K^T ----
        float sfr[4][4];
#pragma unroll
        for (int ni = 0; ni < 4; ni++)
#pragma unroll
            for (int j = 0; j < 4; j++) sfr[ni][j] = 0.f;
#pragma unroll
        for (int kk = 0; kk < 4; kk++) {
#pragma unroll
            for (int ni = 0; ni < 4; ni++) {
                int bb = (warpN + ni * 8 + g) * KST + kk * 8 + c;
                unsigned bf[2] = { kcur[bb], kcur[bb + 4] };
                mma8(sfr[ni], qf[kk], bf);
            }
        }

        // ---- bias + exp + mask; z -> smem; row sums ----
        const bool diag = (kt == qi);
        const int qrow0 = q0 + warpM + g, qrow1 = qrow0 + 8;
        float rsum0 = 0.f, rsum1 = 0.f;
#pragma unroll
        for (int ni = 0; ni < 4; ni++) {
            int tc0 = t0 + warpN + ni * 8 + 2 * c;
            float2 d0 = *(const float2*)(dist + (size_t)(b * SS + qrow0) * SS + tc0);
            float2 d1 = *(const float2*)(dist + (size_t)(b * SS + qrow1) * SS + tc0);
            float z00 = __expf(sfr[ni][0] + __expf(-om * d0.x) - 1.f);
            float z01 = __expf(sfr[ni][1] + __expf(-om * d0.y) - 1.f);
            float z10 = __expf(sfr[ni][2] + __expf(-om * d1.x) - 1.f);
            float z11 = __expf(sfr[ni][3] + __expf(-om * d1.y) - 1.f);
            if (diag) {
                if (tc0     > qrow0) z00 = 0.f;
                if (tc0 + 1 > qrow0) z01 = 0.f;
                if (tc0     > qrow1) z10 = 0.f;
                if (tc0 + 1 > qrow1) z11 = 0.f;
            }
            rsum0 += z00 + z01;
            rsum1 += z10 + z11;
            int zc = warpN + ni * 8 + 2 * c;
            zs[(warpM + g) * ZST + zc]     = z00;
            zs[(warpM + g) * ZST + zc + 1] = z01;
            zs[(warpM + g + 8) * ZST + zc]     = z10;
            zs[(warpM + g + 8) * ZST + zc + 1] = z11;
        }
        rsum0 += __shfl_xor_sync(0xffffffffu, rsum0, 1);
        rsum0 += __shfl_xor_sync(0xffffffffu, rsum0, 2);
        rsum1 += __shfl_xor_sync(0xffffffffu, rsum1, 1);
        rsum1 += __shfl_xor_sync(0xffffffffu, rsum1, 2);
        if (c == 0) {
            atomicAdd(&rs[warpM + g], rsum0);
            atomicAdd(&rs[warpM + g + 8], rsum1);
        }
        __syncthreads();

        // ---- O += Z V ----
        const unsigned* zu = (const unsigned*)zs;
#pragma unroll
        for (int kk = 0; kk < 64; kk += 8) {
            unsigned af[4];
            int ba = (warpM + g) * ZST + kk + c;
            af[0] = zu[ba];           af[1] = zu[ba + 8 * ZST];
            af[2] = zu[ba + 4];       af[3] = zu[ba + 8 * ZST + 4];
#pragma unroll
            for (int ni = 0; ni < 4; ni++) {
                int bb = (kk + c) * VST + warpN + ni * 8 + g;
                unsigned bf[2] = { vcur[bb], vcur[bb + 4 * VST] };
                mma8(oacc[ni], af, bf);
            }
        }
        st ^= 1;
    }

    const float inv0 = 1.f / (rs[warpM + g] + 1.f);
    const float inv1 = 1.f / (rs[warpM + g + 8] + 1.f);
#pragma unroll
    for (int ni = 0; ni < 4; ni++) {
        int col = h * 64 + warpN + ni * 8 + 2 * c;
        float* op0 = yout + (size_t)(b * SS + q0 + warpM + g) * 512 + col;
        float* op1 = yout + (size_t)(b * SS + q0 + warpM + g + 8) * 512 + col;
        *(float2*)op0 = make_float2(oacc[ni][0] * inv0, oacc[ni][1] * inv0);
        *(float2*)op1 = make_float2(oacc[ni][2] * inv1, oacc[ni][3] * inv1);
    }
}

// ---------------- residual add + LayerNorm over 512 ----------------
__global__ __launch_bounds__(128) void add_ln_kernel(
    const float* __restrict__ A, const float* __restrict__ Bs,
    const float* __restrict__ w, const float* __restrict__ bias,
    float* __restrict__ out)
{
    const int row = blockIdx.x;
    const int t = threadIdx.x;
    __shared__ float red[8];

    float4 a4 = *(const float4*)(A  + (size_t)row * 512 + t * 4);
    float4 b4 = *(const float4*)(Bs + (size_t)row * 512 + t * 4);
    float v0 = a4.x + b4.x, v1 = a4.y + b4.y, v2 = a4.z + b4.z, v3 = a4.w + b4.w;

    float s = v0 + v1 + v2 + v3;
#pragma unroll
    for (int o = 16; o > 0; o >>= 1) s += __shfl_xor_sync(0xffffffffu, s, o);
    int wid = t >> 5, lane = t & 31;
    if (!lane) red[wid] = s;
    __syncthreads();
    float mean = (red[0] + red[1] + red[2] + red[3]) * (1.f / 512.f);

    float d0 = v0 - mean, d1 = v1 - mean, d2 = v2 - mean, d3 = v3 - mean;
    float sv = d0*d0 + d1*d1 + d2*d2 + d3*d3;
#pragma unroll
    for (int o = 16; o > 0; o >>= 1) sv += __shfl_xor_sync(0xffffffffu, sv, o);
    if (!lane) red[4 + wid] = sv;
    __syncthreads();
    float var = (red[4] + red[5] + red[6] + red[7]) * (1.f / 512.f);
    float rstd = rsqrtf(var + 1e-5f);

    float4 w4  = *(const float4*)(w    + t * 4);
    float4 bb4 = *(const float4*)(bias + t * 4);
    float4 o4;
    o4.x = d0 * rstd * w4.x + bb4.x;
    o4.y = d1 * rstd * w4.y + bb4.y;
    o4.z = d2 * rstd * w4.z + bb4.z;
    o4.w = d3 * rstd * w4.w + bb4.w;
    *(float4*)(out + (size_t)row * 512 + t * 4) = o4;
}

// ---------------- launch ----------------
extern "C" void kernel_launch(void* const* d_in, const int* in_sizes, int n_in,
                              void* d_out, int out_size)
{
    const float* x     = (const float*)d_in[0];
    const float* dist  = (const float*)d_in[2];
    const float* Wq    = (const float*)d_in[3];
    const float* Wk    = (const float*)d_in[4];
    const float* Wv    = (const float*)d_in[5];
    const float* omega = (const float*)d_in[6];
    const float* Wo    = (const float*)d_in[7];
    const float* bo    = (const float*)d_in[8];
    const float* Wf    = (const float*)d_in[9];
    const float* bf    = (const float*)d_in[10];
    const float* l1w   = (const float*)d_in[11];
    const float* l1b   = (const float*)d_in[12];
    const float* l2w   = (const float*)d_in[13];
    const float* l2b   = (const float*)d_in[14];
    float* out = (float*)d_out;

    float *gq, *gk, *gv, *gy, *gt1, *gz1, *gt2;
    cudaGetSymbolAddress((void**)&gq,  g_q);
    cudaGetSymbolAddress((void**)&gk,  g_k);
    cudaGetSymbolAddress((void**)&gv,  g_v);
    cudaGetSymbolAddress((void**)&gy,  g_y);
    cudaGetSymbolAddress((void**)&gt1, g_t1);
    cudaGetSymbolAddress((void**)&gz1, g_z1);
    cudaGetSymbolAddress((void**)&gt2, g_t2);

    const int ATT_SMEM_BYTES = ATT_WORDS * 4;   // 82176
    cudaFuncSetAttribute(attn2, cudaFuncAttributeMaxDynamicSharedMemorySize,
                         ATT_SMEM_BYTES);

    // fused QKV projections + per-head l2norm epilogue
    gemm_k<true><<<dim3(8, 64), 256>>>(x, Wq, Wk, Wv, nullptr, gq, gk, gv, 0, 512, 0);

    // fused attention
    attn2<<<dim3(HH, SS / 64, BB), 256, ATT_SMEM_BYTES>>>(gq, gk, gv, dist, omega, gy);

    // output projection + LN1
    gemm_k<false><<<dim3(4, 64), 256>>>(gy, Wo, nullptr, nullptr, bo,
                                        gt1, nullptr, nullptr, 512, 512, 0);
    add_ln_kernel<<<NTOK, 128>>>(x, gt1, l1w, l1b, gz1);

    // FFN + leaky relu + LN2
    gemm_k<false><<<dim3(4, 64), 256>>>(gz1, Wf, nullptr, nullptr, bf,
                                        gt2, nullptr, nullptr, 512, 512, 1);
    add_ln_kernel<<<NTOK, 128>>>(gz1, gt2, l2w, l2b, out);
}

// round 6
// speedup vs baseline: 3.0743x; 1.1244x over previous
#include <cuda_runtime.h>
#include <math.h>

#define BB 8
#define SS 1024
#define HH 8
#define NTOK 8192

// ---------------- device scratch ----------------
__device__ float g_q [NTOK*256];   // [token][h*32+k], l2-normalized
__device__ float g_k [NTOK*256];
__device__ float g_v [NTOK*512];   // [token][h*64+c]
__device__ float g_y [NTOK*512];
__device__ float g_t1[NTOK*512];
__device__ float g_z1[NTOK*512];
__device__ float g_t2[NTOK*512];

// ---------------- primitives ----------------
__device__ __forceinline__ void mma8(float* c, const unsigned* a, const unsigned* b) {
    asm volatile(
        "mma.sync.aligned.m16n8k8.row.col.f32.tf32.tf32.f32 "
        "{%0,%1,%2,%3},{%4,%5,%6,%7},{%8,%9},{%0,%1,%2,%3};"
        : "+f"(c[0]), "+f"(c[1]), "+f"(c[2]), "+f"(c[3])
        : "r"(a[0]), "r"(a[1]), "r"(a[2]), "r"(a[3]), "r"(b[0]), "r"(b[1]));
}
// x4 b16 ldmatrix: for tf32 data, lane l must address row (R + (l&15)), k-col (K + (l>>4)*4).
// Then r0..r3 = A-frag a0..a3 of an m16k8 tile, or {r0,r2}/{r1,r3} = B-frags of n8-tiles R / R+8.
__device__ __forceinline__ void ldsm4(unsigned* r, unsigned addr) {
    asm volatile("ldmatrix.sync.aligned.m8n8.x4.shared.b16 {%0,%1,%2,%3}, [%4];"
        : "=r"(r[0]), "=r"(r[1]), "=r"(r[2]), "=r"(r[3]) : "r"(addr));
}
__device__ __forceinline__ void cpa16(unsigned dst, const void* src) {
    asm volatile("cp.async.cg.shared.global [%0], [%1], 16;\n" :: "r"(dst), "l"(src));
}
#define CP_COMMIT asm volatile("cp.async.commit_group;\n" ::: "memory")
#define CP_WAIT0  asm volatile("cp.async.wait_group 0;\n" ::: "memory")

// ---------------- GEMM: C[M,N] = A[M,K] * W[N,K]^T ----------------
// CTA 128x128, 8 warps (4m x 2n), warp tile 32x64, 2-stage cp.async, k-chunk 32, ldmatrix frags.
#define GST 36
#define GSTG (128*GST)
#define GEMM_SMEM_BYTES (4*GSTG*4)

template<bool QKV>
__global__ __launch_bounds__(256, 2) void gemm_k(
    const float* __restrict__ A, const float* __restrict__ W0,
    const float* __restrict__ W1, const float* __restrict__ W2,
    const float* __restrict__ bias,
    float* __restrict__ C0, float* __restrict__ C1, float* __restrict__ C2,
    int Ngen, int K, int act)
{
    extern __shared__ unsigned gsm[];
    unsigned* Asm = gsm;            // [2][128][36]
    unsigned* Wsm = gsm + 2*GSTG;   // [2][128][36]

    const int tid = threadIdx.x, warp = tid >> 5, lane = tid & 31;
    const int g = lane >> 2, c = lane & 3;
    const int lrow = lane & 15, lk4 = (lane >> 4) << 2;
    const int warpM = (warp >> 1) * 32, warpN = (warp & 1) * 64;
    const int m0 = blockIdx.y * 128, bx = blockIdx.x;

    const float* W; float* C; int Nout, col0; bool norm = false;
    if (QKV) {
        if (bx < 2)      { W = W0; C = C0; Nout = 256; col0 = bx * 128;       norm = true; }
        else if (bx < 4) { W = W1; C = C1; Nout = 256; col0 = (bx - 2) * 128; norm = true; }
        else             { W = W2; C = C2; Nout = 512; col0 = (bx - 4) * 128; }
    } else { W = W0; C = C0; Nout = Ngen; col0 = bx * 128; }

    const unsigned sA = (unsigned)__cvta_generic_to_shared(Asm);
    const unsigned sW = (unsigned)__cvta_generic_to_shared(Wsm);

    auto pre = [&](int kc, int st) {
        const int k0 = kc * 32;
#pragma unroll
        for (int i = 0; i < 4; i++) {
            int slot = tid + i * 256;           // 1024 slots = 128 rows x 8 x 16B
            int row = slot >> 3, ch = (slot & 7) * 4;
            cpa16(sA + (unsigned)(st * GSTG + row * GST + ch) * 4,
                  A + (size_t)(m0 + row) * K + k0 + ch);
            cpa16(sW + (unsigned)(st * GSTG + row * GST + ch) * 4,
                  W + (size_t)(col0 + row) * K + k0 + ch);
        }
    };

    float acc[2][8][4];
#pragma unroll
    for (int mi = 0; mi < 2; mi++)
#pragma unroll
        for (int ni = 0; ni < 8; ni++)
#pragma unroll
            for (int j = 0; j < 4; j++) acc[mi][ni][j] = 0.f;

    const int NC = K / 32;
    pre(0, 0); CP_COMMIT;
    int st = 0;
    for (int kc = 0; kc < NC; kc++) {
        CP_WAIT0;
        __syncthreads();
        if (kc + 1 < NC) pre(kc + 1, st ^ 1);
        CP_COMMIT;
        const unsigned aofs = st * GSTG, wofs = st * GSTG;
#pragma unroll
        for (int kk = 0; kk < 32; kk += 8) {
            unsigned af[2][4];
#pragma unroll
            for (int mi = 0; mi < 2; mi++)
                ldsm4(af[mi], sA + (unsigned)(aofs + (warpM + mi * 16 + lrow) * GST + kk + lk4) * 4);
            unsigned bq[4][4];
#pragma unroll
            for (int p = 0; p < 4; p++)
                ldsm4(bq[p], sW + (unsigned)(wofs + (warpN + p * 16 + lrow) * GST + kk + lk4) * 4);
#pragma unroll
            for (int ni = 0; ni < 8; ni++) {
                unsigned bf[2] = { bq[ni >> 1][ni & 1], bq[ni >> 1][2 + (ni & 1)] };
#pragma unroll
                for (int mi = 0; mi < 2; mi++) mma8(acc[mi][ni], af[mi], bf);
            }
        }
        st ^= 1;
    }

#pragma unroll
    for (int mi = 0; mi < 2; mi++) {
        float r0A = 1.f, r0B = 1.f, r1A = 1.f, r1B = 1.f;
        if (QKV && norm) {
            float a0 = 0.f, a1 = 0.f, b0 = 0.f, b1 = 0.f;
#pragma unroll
            for (int ni = 0; ni < 4; ni++) {
                a0 += acc[mi][ni][0]*acc[mi][ni][0] + acc[mi][ni][1]*acc[mi][ni][1];
                a1 += acc[mi][ni][2]*acc[mi][ni][2] + acc[mi][ni][3]*acc[mi][ni][3];
            }
#pragma unroll
            for (int ni = 4; ni < 8; ni++) {
                b0 += acc[mi][ni][0]*acc[mi][ni][0] + acc[mi][ni][1]*acc[mi][ni][1];
                b1 += acc[mi][ni][2]*acc[mi][ni][2] + acc[mi][ni][3]*acc[mi][ni][3];
            }
            a0 += __shfl_xor_sync(0xffffffffu, a0, 1); a0 += __shfl_xor_sync(0xffffffffu, a0, 2);
            a1 += __shfl_xor_sync(0xffffffffu, a1, 1); a1 += __shfl_xor_sync(0xffffffffu, a1, 2);
            b0 += __shfl_xor_sync(0xffffffffu, b0, 1); b0 += __shfl_xor_sync(0xffffffffu, b0, 2);
            b1 += __shfl_xor_sync(0xffffffffu, b1, 1); b1 += __shfl_xor_sync(0xffffffffu, b1, 2);
            r0A = 1.f / fmaxf(sqrtf(a0), 1e-12f);
            r1A = 1.f / fmaxf(sqrtf(a1), 1e-12f);
            r0B = 1.f / fmaxf(sqrtf(b0), 1e-12f);
            r1B = 1.f / fmaxf(sqrtf(b1), 1e-12f);
        }
        const int row0 = m0 + warpM + mi * 16 + g;
#pragma unroll
        for (int ni = 0; ni < 8; ni++) {
            const int col = col0 + warpN + ni * 8 + 2 * c;
            float o0 = acc[mi][ni][0], o1 = acc[mi][ni][1];
            float o2 = acc[mi][ni][2], o3 = acc[mi][ni][3];
            if (QKV) {
                if (norm) {
                    float ra = (ni < 4) ? r0A : r0B;
                    float rb = (ni < 4) ? r1A : r1B;
                    o0 *= ra; o1 *= ra; o2 *= rb; o3 *= rb;
                }
            } else {
                float bx_ = bias[col], by_ = bias[col + 1];
                o0 += bx_; o1 += by_; o2 += bx_; o3 += by_;
                if (act) {
                    o0 = o0 > 0.f ? o0 : 0.01f * o0;
                    o1 = o1 > 0.f ? o1 : 0.01f * o1;
                    o2 = o2 > 0.f ? o2 : 0.01f * o2;
                    o3 = o3 > 0.f ? o3 : 0.01f * o3;
                }
            }
            *(float2*)&C[(size_t)row0 * Nout + col]       = make_float2(o0, o1);
            *(float2*)&C[(size_t)(row0 + 8) * Nout + col] = make_float2(o2, o3);
        }
    }
}

// ---------------- fused attention: CTA tile 128(q) x 64(t), warp tile 32x32 ----
#define KST 36
#define VST 72
#define DST 68
#define ZST 68
#define ATT_WORDS (128*KST + 2*64*KST + 2*64*VST + 2*128*DST + 128*ZST + 128)
#define ATT_SMEM_BYTES (ATT_WORDS*4)

__global__ __launch_bounds__(256) void attn3(
    const float* __restrict__ qn, const float* __restrict__ kn,
    const float* __restrict__ vf, const float* __restrict__ dist,
    const float* __restrict__ omega, float* __restrict__ yout)
{
    extern __shared__ unsigned sm[];
    unsigned* qs = sm;                          // [128][36]
    unsigned* ks = qs + 128*KST;                // [2][64][36]
    unsigned* vs = ks + 2*64*KST;               // [2][64][72]
    float*    ds = (float*)(vs + 2*64*VST);     // [2][128][68]
    float*    zs = ds + 2*128*DST;              // [128][68]
    float*    rs = zs + 128*ZST;                // [128]

    const int h = blockIdx.x, b = blockIdx.z;
    const int qi = (int)(gridDim.y - 1 - blockIdx.y);   // heavy CTAs first
    const int q0 = qi * 128;
    const int tid = threadIdx.x, warp = tid >> 5, lane = tid & 31;
    const int g = lane >> 2, c = lane & 3;
    const int lrow = lane & 15, lk4 = (lane >> 4) << 2;
    const int warpM = (warp >> 1) * 32, warpN = (warp & 1) * 32;
    const float om = omega[h];
    if (tid < 128) rs[tid] = 0.f;

    const unsigned sq = (unsigned)__cvta_generic_to_shared(qs);
    const unsigned sk = (unsigned)__cvta_generic_to_shared(ks);
    const unsigned sv = (unsigned)__cvta_generic_to_shared(vs);
    const unsigned sd = (unsigned)__cvta_generic_to_shared(ds);
    const unsigned sz = (unsigned)__cvta_generic_to_shared(zs);

    auto ldK = [&](int st, int t0) {
#pragma unroll
        for (int i = 0; i < 2; i++) {
            int slot = tid + i * 256, row = slot >> 3, ch = (slot & 7) * 4;
            cpa16(sk + (unsigned)(st * 64 * KST + row * KST + ch) * 4,
                  kn + (size_t)(b * SS + t0 + row) * 256 + h * 32 + ch);
        }
    };
    auto ldV = [&](int st, int t0) {
#pragma unroll
        for (int i = 0; i < 4; i++) {
            int slot = tid + i * 256, row = slot >> 4, ch = (slot & 15) * 4;
            cpa16(sv + (unsigned)(st * 64 * VST + row * VST + ch) * 4,
                  vf + (size_t)(b * SS + t0 + row) * 512 + h * 64 + ch);
        }
    };
    auto ldD = [&](int st, int t0) {
#pragma unroll
        for (int i = 0; i < 8; i++) {
            int slot = tid + i * 256, row = slot >> 4, ch = (slot & 15) * 4;
            cpa16(sd + (unsigned)(st * 128 * DST + row * DST + ch) * 4,
                  dist + (size_t)(b * SS + q0 + row) * SS + t0 + ch);
        }
    };
    // Q tile (128 x 32)
#pragma unroll
    for (int i = 0; i < 4; i++) {
        int slot = tid + i * 256, row = slot >> 3, ch = (slot & 7) * 4;
        cpa16(sq + (unsigned)(row * KST + ch) * 4,
              qn + (size_t)(b * SS + q0 + row) * 256 + h * 32 + ch);
    }
    ldK(0, 0); ldV(0, 0); ldD(0, 0); CP_COMMIT;

    unsigned qf[2][4][4];
    float oacc[2][4][4];
#pragma unroll
    for (int mi = 0; mi < 2; mi++)
#pragma unroll
        for (int ni = 0; ni < 4; ni++)
#pragma unroll
            for (int j = 0; j < 4; j++) oacc[mi][ni][j] = 0.f;

    const int nkt = 2 * qi + 2;
    int st = 0;
    for (int kt = 0; kt < nkt; kt++) {
        const int t0 = kt * 64;
        CP_WAIT0;
        __syncthreads();
        if (kt == 0) {
#pragma unroll
            for (int mi = 0; mi < 2; mi++)
#pragma unroll
                for (int kk = 0; kk < 4; kk++)
                    ldsm4(qf[mi][kk],
                          sq + (unsigned)((warpM + mi * 16 + lrow) * KST + kk * 8 + lk4) * 4);
        }
        if (kt + 1 < nkt) { ldK(st ^ 1, t0 + 64); ldV(st ^ 1, t0 + 64); ldD(st ^ 1, t0 + 64); }
        CP_COMMIT;

        const unsigned kof = st * 64 * KST, vof = st * 64 * VST;
        const float* dcur = ds + st * 128 * DST;

        // ---- S = Q K^T ----
        float sfr[2][4][4];
#pragma unroll
        for (int mi = 0; mi < 2; mi++)
#pragma unroll
            for (int ni = 0; ni < 4; ni++)
#pragma unroll
                for (int j = 0; j < 4; j++) sfr[mi][ni][j] = 0.f;
#pragma unroll
        for (int kk = 0; kk < 4; kk++) {
            unsigned bq[2][4];
#pragma unroll
            for (int p = 0; p < 2; p++)
                ldsm4(bq[p], sk + (unsigned)(kof + (warpN + p * 16 + lrow) * KST + kk * 8 + lk4) * 4);
#pragma unroll
            for (int ni = 0; ni < 4; ni++) {
                unsigned bf[2] = { bq[ni >> 1][ni & 1], bq[ni >> 1][2 + (ni & 1)] };
#pragma unroll
                for (int mi = 0; mi < 2; mi++) mma8(sfr[mi][ni], qf[mi][kk], bf);
            }
        }

        // ---- bias + exp + mask; z -> smem; row sums ----
        const bool needmask = (kt >= 2 * qi);
#pragma unroll
        for (int mi = 0; mi < 2; mi++) {
            const int rl0 = warpM + mi * 16 + g;
            const int qrow0 = q0 + rl0, qrow1 = qrow0 + 8;
            float rsum0 = 0.f, rsum1 = 0.f;
#pragma unroll
            for (int ni = 0; ni < 4; ni++) {
                const int tcl = warpN + ni * 8 + 2 * c;
                const int tc0 = t0 + tcl;
                float2 d0 = *(const float2*)(dcur + rl0 * DST + tcl);
                float2 d1 = *(const float2*)(dcur + (rl0 + 8) * DST + tcl);
                float z00 = __expf(sfr[mi][ni][0] + __expf(-om * d0.x) - 1.f);
                float z01 = __expf(sfr[mi][ni][1] + __expf(-om * d0.y) - 1.f);
                float z10 = __expf(sfr[mi][ni][2] + __expf(-om * d1.x) - 1.f);
                float z11 = __expf(sfr[mi][ni][3] + __expf(-om * d1.y) - 1.f);
                if (needmask) {
                    if (tc0     > qrow0) z00 = 0.f;
                    if (tc0 + 1 > qrow0) z01 = 0.f;
                    if (tc0     > qrow1) z10 = 0.f;
                    if (tc0 + 1 > qrow1) z11 = 0.f;
                }
                rsum0 += z00 + z01;
                rsum1 += z10 + z11;
                *(float2*)(zs + rl0 * ZST + tcl)       = make_float2(z00, z01);
                *(float2*)(zs + (rl0 + 8) * ZST + tcl) = make_float2(z10, z11);
            }
            rsum0 += __shfl_xor_sync(0xffffffffu, rsum0, 1);
            rsum0 += __shfl_xor_sync(0xffffffffu, rsum0, 2);
            rsum1 += __shfl_xor_sync(0xffffffffu, rsum1, 1);
            rsum1 += __shfl_xor_sync(0xffffffffu, rsum1, 2);
            if (c == 0) {
                atomicAdd(&rs[rl0], rsum0);
                atomicAdd(&rs[rl0 + 8], rsum1);
            }
        }
        __syncthreads();   // z from both n-warps visible

        // ---- O += Z V ----
#pragma unroll
        for (int kk = 0; kk < 8; kk++) {
            unsigned zf[2][4];
#pragma unroll
            for (int mi = 0; mi < 2; mi++)
                ldsm4(zf[mi], sz + (unsigned)((warpM + mi * 16 + lrow) * ZST + kk * 8 + lk4) * 4);
#pragma unroll
            for (int ni = 0; ni < 4; ni++) {
                int bb = vof + (kk * 8 + c) * VST + warpN + ni * 8 + g;
                unsigned bf[2] = { vs[bb], vs[bb + 4 * VST] };
#pragma unroll
                for (int mi = 0; mi < 2; mi++) mma8(oacc[mi][ni], zf[mi], bf);
            }
        }
        st ^= 1;
    }

    // ---- normalize by (rowsum + 1), write concat layout ----
#pragma unroll
    for (int mi = 0; mi < 2; mi++) {
        const int rl0 = warpM + mi * 16 + g;
        const float inv0 = 1.f / (rs[rl0] + 1.f);
        const float inv1 = 1.f / (rs[rl0 + 8] + 1.f);
#pragma unroll
        for (int ni = 0; ni < 4; ni++) {
            int col = h * 64 + warpN + ni * 8 + 2 * c;
            *(float2*)(yout + (size_t)(b * SS + q0 + rl0) * 512 + col) =
                make_float2(oacc[mi][ni][0] * inv0, oacc[mi][ni][1] * inv0);
            *(float2*)(yout + (size_t)(b * SS + q0 + rl0 + 8) * 512 + col) =
                make_float2(oacc[mi][ni][2] * inv1, oacc[mi][ni][3] * inv1);
        }
    }
}

// ---------------- residual add + LayerNorm over 512 ----------------
__global__ __launch_bounds__(128) void add_ln_kernel(
    const float* __restrict__ A, const float* __restrict__ Bs,
    const float* __restrict__ w, const float* __restrict__ bias,
    float* __restrict__ out)
{
    const int row = blockIdx.x;
    const int t = threadIdx.x;
    __shared__ float red[8];

    float4 a4 = *(const float4*)(A  + (size_t)row * 512 + t * 4);
    float4 b4 = *(const float4*)(Bs + (size_t)row * 512 + t * 4);
    float v0 = a4.x + b4.x, v1 = a4.y + b4.y, v2 = a4.z + b4.z, v3 = a4.w + b4.w;

    float s = v0 + v1 + v2 + v3;
#pragma unroll
    for (int o = 16; o > 0; o >>= 1) s += __shfl_xor_sync(0xffffffffu, s, o);
    int wid = t >> 5, lane = t & 31;
    if (!lane) red[wid] = s;
    __syncthreads();
    float mean = (red[0] + red[1] + red[2] + red[3]) * (1.f / 512.f);

    float d0 = v0 - mean, d1 = v1 - mean, d2 = v2 - mean, d3 = v3 - mean;
    float sv = d0*d0 + d1*d1 + d2*d2 + d3*d3;
#pragma unroll
    for (int o = 16; o > 0; o >>= 1) sv += __shfl_xor_sync(0xffffffffu, sv, o);
    if (!lane) red[4 + wid] = sv;
    __syncthreads();
    float var = (red[4] + red[5] + red[6] + red[7]) * (1.f / 512.f);
    float rstd = rsqrtf(var + 1e-5f);

    float4 w4  = *(const float4*)(w    + t * 4);
    float4 bb4 = *(const float4*)(bias + t * 4);
    float4 o4;
    o4.x = d0 * rstd * w4.x + bb4.x;
    o4.y = d1 * rstd * w4.y + bb4.y;
    o4.z = d2 * rstd * w4.z + bb4.z;
    o4.w = d3 * rstd * w4.w + bb4.w;
    *(float4*)(out + (size_t)row * 512 + t * 4) = o4;
}

// ---------------- launch ----------------
extern "C" void kernel_launch(void* const* d_in, const int* in_sizes, int n_in,
                              void* d_out, int out_size)
{
    const float* x     = (const float*)d_in[0];
    const float* dist  = (const float*)d_in[2];
    const float* Wq    = (const float*)d_in[3];
    const float* Wk    = (const float*)d_in[4];
    const float* Wv    = (const float*)d_in[5];
    const float* omega = (const float*)d_in[6];
    const float* Wo    = (const float*)d_in[7];
    const float* bo    = (const float*)d_in[8];
    const float* Wf    = (const float*)d_in[9];
    const float* bf    = (const float*)d_in[10];
    const float* l1w   = (const float*)d_in[11];
    const float* l1b   = (const float*)d_in[12];
    const float* l2w   = (const float*)d_in[13];
    const float* l2b   = (const float*)d_in[14];
    float* out = (float*)d_out;

    float *gq, *gk, *gv, *gy, *gt1, *gz1, *gt2;
    cudaGetSymbolAddress((void**)&gq,  g_q);
    cudaGetSymbolAddress((void**)&gk,  g_k);
    cudaGetSymbolAddress((void**)&gv,  g_v);
    cudaGetSymbolAddress((void**)&gy,  g_y);
    cudaGetSymbolAddress((void**)&gt1, g_t1);
    cudaGetSymbolAddress((void**)&gz1, g_z1);
    cudaGetSymbolAddress((void**)&gt2, g_t2);

    cudaFuncSetAttribute(gemm_k<true>,  cudaFuncAttributeMaxDynamicSharedMemorySize, GEMM_SMEM_BYTES);
    cudaFuncSetAttribute(gemm_k<false>, cudaFuncAttributeMaxDynamicSharedMemorySize, GEMM_SMEM_BYTES);
    cudaFuncSetAttribute(attn3, cudaFuncAttributeMaxDynamicSharedMemorySize, ATT_SMEM_BYTES);

    // fused QKV projections + per-head l2norm epilogue
    gemm_k<true><<<dim3(8, 64), 256, GEMM_SMEM_BYTES>>>(x, Wq, Wk, Wv, nullptr,
                                                        gq, gk, gv, 0, 512, 0);

    // fused attention (128x64 tiles)
    attn3<<<dim3(HH, SS / 128, BB), 256, ATT_SMEM_BYTES>>>(gq, gk, gv, dist, omega, gy);

    // output projection + LN1
    gemm_k<false><<<dim3(4, 64), 256, GEMM_SMEM_BYTES>>>(gy, Wo, nullptr, nullptr, bo,
                                                         gt1, nullptr, nullptr, 512, 512, 0);
    add_ln_kernel<<<NTOK, 128>>>(x, gt1, l1w, l1b, gz1);

    // FFN + leaky relu + LN2
    gemm_k<false><<<dim3(4, 64), 256, GEMM_SMEM_BYTES>>>(gz1, Wf, nullptr, nullptr, bf,
                                                         gt2, nullptr, nullptr, 512, 512, 1);
    add_ln_kernel<<<NTOK, 128>>>(gz1, gt2, l2w, l2b, out);
}

// round 7
// speedup vs baseline: 3.3646x; 1.0945x over previous
#include <cuda_runtime.h>
#include <math.h>

#define BB 8
#define SS 1024
#define HH 8
#define NTOK 8192

// ---------------- device scratch ----------------
__device__ float g_q [NTOK*256];   // [token][h*32+k], l2-normalized
__device__ float g_k [NTOK*256];
__device__ float g_v [NTOK*512];   // [token][h*64+c]
__device__ float g_y [NTOK*512];
__device__ float g_t1[NTOK*512];
__device__ float g_z1[NTOK*512];
__device__ float g_t2[NTOK*512];

// ---------------- primitives ----------------
__device__ __forceinline__ void mma8(float* c, const unsigned* a, const unsigned* b) {
    asm volatile(
        "mma.sync.aligned.m16n8k8.row.col.f32.tf32.tf32.f32 "
        "{%0,%1,%2,%3},{%4,%5,%6,%7},{%8,%9},{%0,%1,%2,%3};"
        : "+f"(c[0]), "+f"(c[1]), "+f"(c[2]), "+f"(c[3])
        : "r"(a[0]), "r"(a[1]), "r"(a[2]), "r"(a[3]), "r"(b[0]), "r"(b[1]));
}
// x4 b16 ldmatrix on tf32 data: lane l addresses row (R + (l&15)), k-col (K + (l>>4)*4).
__device__ __forceinline__ void ldsm4(unsigned* r, unsigned addr) {
    asm volatile("ldmatrix.sync.aligned.m8n8.x4.shared.b16 {%0,%1,%2,%3}, [%4];"
        : "=r"(r[0]), "=r"(r[1]), "=r"(r[2]), "=r"(r[3]) : "r"(addr));
}
__device__ __forceinline__ void cpa16(unsigned dst, const void* src) {
    asm volatile("cp.async.cg.shared.global [%0], [%1], 16;\n" :: "r"(dst), "l"(src));
}
#define CP_COMMIT asm volatile("cp.async.commit_group;\n" ::: "memory")
#define CP_WAIT0  asm volatile("cp.async.wait_group 0;\n" ::: "memory")

// ---------------- GEMM: C[M,N] = A[M,K] * W[N,K]^T ----------------
#define GST 36
#define GSTG (128*GST)
#define GEMM_SMEM_BYTES (4*GSTG*4)

template<bool QKV>
__global__ __launch_bounds__(256, 2) void gemm_k(
    const float* __restrict__ A, const float* __restrict__ W0,
    const float* __restrict__ W1, const float* __restrict__ W2,
    const float* __restrict__ bias,
    float* __restrict__ C0, float* __restrict__ C1, float* __restrict__ C2,
    int Ngen, int K, int act)
{
    extern __shared__ unsigned gsm[];
    unsigned* Asm = gsm;            // [2][128][36]
    unsigned* Wsm = gsm + 2*GSTG;   // [2][128][36]

    const int tid = threadIdx.x, warp = tid >> 5, lane = tid & 31;
    const int g = lane >> 2, c = lane & 3;
    const int lrow = lane & 15, lk4 = (lane >> 4) << 2;
    const int warpM = (warp >> 1) * 32, warpN = (warp & 1) * 64;
    const int m0 = blockIdx.y * 128, bx = blockIdx.x;

    const float* W; float* C; int Nout, col0; bool norm = false;
    if (QKV) {
        if (bx < 2)      { W = W0; C = C0; Nout = 256; col0 = bx * 128;       norm = true; }
        else if (bx < 4) { W = W1; C = C1; Nout = 256; col0 = (bx - 2) * 128; norm = true; }
        else             { W = W2; C = C2; Nout = 512; col0 = (bx - 4) * 128; }
    } else { W = W0; C = C0; Nout = Ngen; col0 = bx * 128; }

    const unsigned sA = (unsigned)__cvta_generic_to_shared(Asm);
    const unsigned sW = (unsigned)__cvta_generic_to_shared(Wsm);

    auto pre = [&](int kc, int st) {
        const int k0 = kc * 32;
#pragma unroll
        for (int i = 0; i < 4; i++) {
            int slot = tid + i * 256;
            int row = slot >> 3, ch = (slot & 7) * 4;
            cpa16(sA + (unsigned)(st * GSTG + row * GST + ch) * 4,
                  A + (size_t)(m0 + row) * K + k0 + ch);
            cpa16(sW + (unsigned)(st * GSTG + row * GST + ch) * 4,
                  W + (size_t)(col0 + row) * K + k0 + ch);
        }
    };

    float acc[2][8][4];
#pragma unroll
    for (int mi = 0; mi < 2; mi++)
#pragma unroll
        for (int ni = 0; ni < 8; ni++)
#pragma unroll
            for (int j = 0; j < 4; j++) acc[mi][ni][j] = 0.f;

    const int NC = K / 32;
    pre(0, 0); CP_COMMIT;
    int st = 0;
    for (int kc = 0; kc < NC; kc++) {
        CP_WAIT0;
        __syncthreads();
        if (kc + 1 < NC) pre(kc + 1, st ^ 1);
        CP_COMMIT;
        const unsigned aofs = st * GSTG, wofs = st * GSTG;
#pragma unroll
        for (int kk = 0; kk < 32; kk += 8) {
            unsigned af[2][4];
#pragma unroll
            for (int mi = 0; mi < 2; mi++)
                ldsm4(af[mi], sA + (unsigned)(aofs + (warpM + mi * 16 + lrow) * GST + kk + lk4) * 4);
            unsigned bq[4][4];
#pragma unroll
            for (int p = 0; p < 4; p++)
                ldsm4(bq[p], sW + (unsigned)(wofs + (warpN + p * 16 + lrow) * GST + kk + lk4) * 4);
#pragma unroll
            for (int ni = 0; ni < 8; ni++) {
                unsigned bf[2] = { bq[ni >> 1][ni & 1], bq[ni >> 1][2 + (ni & 1)] };
#pragma unroll
                for (int mi = 0; mi < 2; mi++) mma8(acc[mi][ni], af[mi], bf);
            }
        }
        st ^= 1;
    }

#pragma unroll
    for (int mi = 0; mi < 2; mi++) {
        float r0A = 1.f, r0B = 1.f, r1A = 1.f, r1B = 1.f;
        if (QKV && norm) {
            float a0 = 0.f, a1 = 0.f, b0 = 0.f, b1 = 0.f;
#pragma unroll
            for (int ni = 0; ni < 4; ni++) {
                a0 += acc[mi][ni][0]*acc[mi][ni][0] + acc[mi][ni][1]*acc[mi][ni][1];
                a1 += acc[mi][ni][2]*acc[mi][ni][2] + acc[mi][ni][3]*acc[mi][ni][3];
            }
#pragma unroll
            for (int ni = 4; ni < 8; ni++) {
                b0 += acc[mi][ni][0]*acc[mi][ni][0] + acc[mi][ni][1]*acc[mi][ni][1];
                b1 += acc[mi][ni][2]*acc[mi][ni][2] + acc[mi][ni][3]*acc[mi][ni][3];
            }
            a0 += __shfl_xor_sync(0xffffffffu, a0, 1); a0 += __shfl_xor_sync(0xffffffffu, a0, 2);
            a1 += __shfl_xor_sync(0xffffffffu, a1, 1); a1 += __shfl_xor_sync(0xffffffffu, a1, 2);
            b0 += __shfl_xor_sync(0xffffffffu, b0, 1); b0 += __shfl_xor_sync(0xffffffffu, b0, 2);
            b1 += __shfl_xor_sync(0xffffffffu, b1, 1); b1 += __shfl_xor_sync(0xffffffffu, b1, 2);
            r0A = 1.f / fmaxf(sqrtf(a0), 1e-12f);
            r1A = 1.f / fmaxf(sqrtf(a1), 1e-12f);
            r0B = 1.f / fmaxf(sqrtf(b0), 1e-12f);
            r1B = 1.f / fmaxf(sqrtf(b1), 1e-12f);
        }
        const int row0 = m0 + warpM + mi * 16 + g;
#pragma unroll
        for (int ni = 0; ni < 8; ni++) {
            const int col = col0 + warpN + ni * 8 + 2 * c;
            float o0 = acc[mi][ni][0], o1 = acc[mi][ni][1];
            float o2 = acc[mi][ni][2], o3 = acc[mi][ni][3];
            if (QKV) {
                if (norm) {
                    float ra = (ni < 4) ? r0A : r0B;
                    float rb = (ni < 4) ? r1A : r1B;
                    o0 *= ra; o1 *= ra; o2 *= rb; o3 *= rb;
                }
            } else {
                float bx_ = bias[col], by_ = bias[col + 1];
                o0 += bx_; o1 += by_; o2 += bx_; o3 += by_;
                if (act) {
                    o0 = o0 > 0.f ? o0 : 0.01f * o0;
                    o1 = o1 > 0.f ? o1 : 0.01f * o1;
                    o2 = o2 > 0.f ? o2 : 0.01f * o2;
                    o3 = o3 > 0.f ? o3 : 0.01f * o3;
                }
            }
            *(float2*)&C[(size_t)row0 * Nout + col]       = make_float2(o0, o1);
            *(float2*)&C[(size_t)(row0 + 8) * Nout + col] = make_float2(o2, o3);
        }
    }
}

// ---------------- fused attention: CTA 128(q) x 64(t), 2 CTAs/SM ----------------
#define KST 36
#define VST 72
#define ZST 68
#define ATT_WORDS (128*KST + 2*64*KST + 2*64*VST + 128*ZST + 128)
#define ATT_SMEM_BYTES (ATT_WORDS*4)   /* 109056 */

__global__ __launch_bounds__(256, 2) void attn4(
    const float* __restrict__ qn, const float* __restrict__ kn,
    const float* __restrict__ vf, const float* __restrict__ dist,
    const float* __restrict__ omega, float* __restrict__ yout)
{
    extern __shared__ unsigned sm[];
    unsigned* qs = sm;                          // [128][36]
    unsigned* ks = qs + 128*KST;                // [2][64][36]
    unsigned* vs = ks + 2*64*KST;               // [2][64][72]
    float*    zs = (float*)(vs + 2*64*VST);     // [128][68]
    float*    rs = zs + 128*ZST;                // [128]

    const int h = blockIdx.x, b = blockIdx.z;
    const int qi = (int)(gridDim.y - 1 - blockIdx.y);   // heavy CTAs first
    const int q0 = qi * 128;
    const int tid = threadIdx.x, warp = tid >> 5, lane = tid & 31;
    const int g = lane >> 2, c = lane & 3;
    const int lrow = lane & 15, lk4 = (lane >> 4) << 2;
    const int warpM = (warp >> 1) * 32, warpN = (warp & 1) * 32;
    const float om = omega[h];
    if (tid < 128) rs[tid] = 0.f;

    const unsigned sq = (unsigned)__cvta_generic_to_shared(qs);
    const unsigned sk = (unsigned)__cvta_generic_to_shared(ks);
    const unsigned sv = (unsigned)__cvta_generic_to_shared(vs);
    const unsigned sz = (unsigned)__cvta_generic_to_shared(zs);

    auto ldK = [&](int st, int t0) {
#pragma unroll
        for (int i = 0; i < 2; i++) {
            int slot = tid + i * 256, row = slot >> 3, ch = (slot & 7) * 4;
            cpa16(sk + (unsigned)(st * 64 * KST + row * KST + ch) * 4,
                  kn + (size_t)(b * SS + t0 + row) * 256 + h * 32 + ch);
        }
    };
    auto ldV = [&](int st, int t0) {
#pragma unroll
        for (int i = 0; i < 4; i++) {
            int slot = tid + i * 256, row = slot >> 4, ch = (slot & 15) * 4;
            cpa16(sv + (unsigned)(st * 64 * VST + row * VST + ch) * 4,
                  vf + (size_t)(b * SS + t0 + row) * 512 + h * 64 + ch);
        }
    };
    // Q tile (128 x 32)
#pragma unroll
    for (int i = 0; i < 4; i++) {
        int slot = tid + i * 256, row = slot >> 3, ch = (slot & 7) * 4;
        cpa16(sq + (unsigned)(row * KST + ch) * 4,
              qn + (size_t)(b * SS + q0 + row) * 256 + h * 32 + ch);
    }
    ldK(0, 0); ldV(0, 0); CP_COMMIT;

    float oacc[2][4][4];
#pragma unroll
    for (int mi = 0; mi < 2; mi++)
#pragma unroll
        for (int ni = 0; ni < 4; ni++)
#pragma unroll
            for (int j = 0; j < 4; j++) oacc[mi][ni][j] = 0.f;
    // per-thread partial row sums accumulated over ALL tiles (reduced once at end)
    float rsacc[2][2] = {{0.f, 0.f}, {0.f, 0.f}};

    const int nkt = 2 * qi + 2;
    int st = 0;
    for (int kt = 0; kt < nkt; kt++) {
        const int t0 = kt * 64;
        CP_WAIT0;
        __syncthreads();
        if (kt + 1 < nkt) { ldK(st ^ 1, t0 + 64); ldV(st ^ 1, t0 + 64); }
        CP_COMMIT;

        const unsigned kof = st * 64 * KST, vof = st * 64 * VST;

        // ---- S = Q K^T (Q frags reloaded per tile: frees 32 regs for occ=2) ----
        float sfr[2][4][4];
#pragma unroll
        for (int mi = 0; mi < 2; mi++)
#pragma unroll
            for (int ni = 0; ni < 4; ni++)
#pragma unroll
                for (int j = 0; j < 4; j++) sfr[mi][ni][j] = 0.f;
#pragma unroll
        for (int kk = 0; kk < 4; kk++) {
            unsigned af[2][4];
#pragma unroll
            for (int mi = 0; mi < 2; mi++)
                ldsm4(af[mi], sq + (unsigned)((warpM + mi * 16 + lrow) * KST + kk * 8 + lk4) * 4);
            unsigned bq[2][4];
#pragma unroll
            for (int p = 0; p < 2; p++)
                ldsm4(bq[p], sk + (unsigned)(kof + (warpN + p * 16 + lrow) * KST + kk * 8 + lk4) * 4);
#pragma unroll
            for (int ni = 0; ni < 4; ni++) {
                unsigned bf[2] = { bq[ni >> 1][ni & 1], bq[ni >> 1][2 + (ni & 1)] };
#pragma unroll
                for (int mi = 0; mi < 2; mi++) mma8(sfr[mi][ni], af[mi], bf);
            }
        }

        // ---- bias + exp + mask; z -> smem; partial row sums in regs ----
        const bool needmask = (kt >= 2 * qi);
#pragma unroll
        for (int mi = 0; mi < 2; mi++) {
            const int rl0 = warpM + mi * 16 + g;
            const int qrow0 = q0 + rl0, qrow1 = qrow0 + 8;
#pragma unroll
            for (int ni = 0; ni < 4; ni++) {
                const int tcl = warpN + ni * 8 + 2 * c;
                const int tc0 = t0 + tcl;
                float2 d0 = __ldg((const float2*)(dist + (size_t)(b * SS + qrow0) * SS + tc0));
                float2 d1 = __ldg((const float2*)(dist + (size_t)(b * SS + qrow1) * SS + tc0));
                float z00 = __expf(sfr[mi][ni][0] + __expf(-om * d0.x) - 1.f);
                float z01 = __expf(sfr[mi][ni][1] + __expf(-om * d0.y) - 1.f);
                float z10 = __expf(sfr[mi][ni][2] + __expf(-om * d1.x) - 1.f);
                float z11 = __expf(sfr[mi][ni][3] + __expf(-om * d1.y) - 1.f);
                if (needmask) {
                    if (tc0     > qrow0) z00 = 0.f;
                    if (tc0 + 1 > qrow0) z01 = 0.f;
                    if (tc0     > qrow1) z10 = 0.f;
                    if (tc0 + 1 > qrow1) z11 = 0.f;
                }
                rsacc[mi][0] += z00 + z01;
                rsacc[mi][1] += z10 + z11;
                *(float2*)(zs + rl0 * ZST + tcl)       = make_float2(z00, z01);
                *(float2*)(zs + (rl0 + 8) * ZST + tcl) = make_float2(z10, z11);
            }
        }
        __syncthreads();   // z from both n-warps visible

        // ---- O += Z V ----
#pragma unroll
        for (int kk = 0; kk < 8; kk++) {
            unsigned zf[2][4];
#pragma unroll
            for (int mi = 0; mi < 2; mi++)
                ldsm4(zf[mi], sz + (unsigned)((warpM + mi * 16 + lrow) * ZST + kk * 8 + lk4) * 4);
#pragma unroll
            for (int ni = 0; ni < 4; ni++) {
                int bb = vof + (kk * 8 + c) * VST + warpN + ni * 8 + g;
                unsigned bf[2] = { vs[bb], vs[bb + 4 * VST] };
#pragma unroll
                for (int mi = 0; mi < 2; mi++) mma8(oacc[mi][ni], zf[mi], bf);
            }
        }
        st ^= 1;
    }

    // ---- one-time row-sum reduction: quad shuffle + cross-n-warp atomic ----
#pragma unroll
    for (int mi = 0; mi < 2; mi++) {
#pragma unroll
        for (int r = 0; r < 2; r++) {
            rsacc[mi][r] += __shfl_xor_sync(0xffffffffu, rsacc[mi][r], 1);
            rsacc[mi][r] += __shfl_xor_sync(0xffffffffu, rsacc[mi][r], 2);
        }
        if (c == 0) {
            atomicAdd(&rs[warpM + mi * 16 + g], rsacc[mi][0]);
            atomicAdd(&rs[warpM + mi * 16 + g + 8], rsacc[mi][1]);
        }
    }
    __syncthreads();

    // ---- normalize by (rowsum + 1), write concat layout ----
#pragma unroll
    for (int mi = 0; mi < 2; mi++) {
        const int rl0 = warpM + mi * 16 + g;
        const float inv0 = 1.f / (rs[rl0] + 1.f);
        const float inv1 = 1.f / (rs[rl0 + 8] + 1.f);
#pragma unroll
        for (int ni = 0; ni < 4; ni++) {
            int col = h * 64 + warpN + ni * 8 + 2 * c;
            *(float2*)(yout + (size_t)(b * SS + q0 + rl0) * 512 + col) =
                make_float2(oacc[mi][ni][0] * inv0, oacc[mi][ni][1] * inv0);
            *(float2*)(yout + (size_t)(b * SS + q0 + rl0 + 8) * 512 + col) =
                make_float2(oacc[mi][ni][2] * inv1, oacc[mi][ni][3] * inv1);
        }
    }
}

// ---------------- residual add + LayerNorm over 512 ----------------
__global__ __launch_bounds__(128) void add_ln_kernel(
    const float* __restrict__ A, const float* __restrict__ Bs,
    const float* __restrict__ w, const float* __restrict__ bias,
    float* __restrict__ out)
{
    const int row = blockIdx.x;
    const int t = threadIdx.x;
    __shared__ float red[8];

    float4 a4 = *(const float4*)(A  + (size_t)row * 512 + t * 4);
    float4 b4 = *(const float4*)(Bs + (size_t)row * 512 + t * 4);
    float v0 = a4.x + b4.x, v1 = a4.y + b4.y, v2 = a4.z + b4.z, v3 = a4.w + b4.w;

    float s = v0 + v1 + v2 + v3;
#pragma unroll
    for (int o = 16; o > 0; o >>= 1) s += __shfl_xor_sync(0xffffffffu, s, o);
    int wid = t >> 5, lane = t & 31;
    if (!lane) red[wid] = s;
    __syncthreads();
    float mean = (red[0] + red[1] + red[2] + red[3]) * (1.f / 512.f);

    float d0 = v0 - mean, d1 = v1 - mean, d2 = v2 - mean, d3 = v3 - mean;
    float sv = d0*d0 + d1*d1 + d2*d2 + d3*d3;
#pragma unroll
    for (int o = 16; o > 0; o >>= 1) sv += __shfl_xor_sync(0xffffffffu, sv, o);
    if (!lane) red[4 + wid] = sv;
    __syncthreads();
    float var = (red[4] + red[5] + red[6] + red[7]) * (1.f / 512.f);
    float rstd = rsqrtf(var + 1e-5f);

    float4 w4  = *(const float4*)(w    + t * 4);
    float4 bb4 = *(const float4*)(bias + t * 4);
    float4 o4;
    o4.x = d0 * rstd * w4.x + bb4.x;
    o4.y = d1 * rstd * w4.y + bb4.y;
    o4.z = d2 * rstd * w4.z + bb4.z;
    o4.w = d3 * rstd * w4.w + bb4.w;
    *(float4*)(out + (size_t)row * 512 + t * 4) = o4;
}

// ---------------- launch ----------------
extern "C" void kernel_launch(void* const* d_in, const int* in_sizes, int n_in,
                              void* d_out, int out_size)
{
    const float* x     = (const float*)d_in[0];
    const float* dist  = (const float*)d_in[2];
    const float* Wq    = (const float*)d_in[3];
    const float* Wk    = (const float*)d_in[4];
    const float* Wv    = (const float*)d_in[5];
    const float* omega = (const float*)d_in[6];
    const float* Wo    = (const float*)d_in[7];
    const float* bo    = (const float*)d_in[8];
    const float* Wf    = (const float*)d_in[9];
    const float* bf    = (const float*)d_in[10];
    const float* l1w   = (const float*)d_in[11];
    const float* l1b   = (const float*)d_in[12];
    const float* l2w   = (const float*)d_in[13];
    const float* l2b   = (const float*)d_in[14];
    float* out = (float*)d_out;

    float *gq, *gk, *gv, *gy, *gt1, *gz1, *gt2;
    cudaGetSymbolAddress((void**)&gq,  g_q);
    cudaGetSymbolAddress((void**)&gk,  g_k);
    cudaGetSymbolAddress((void**)&gv,  g_v);
    cudaGetSymbolAddress((void**)&gy,  g_y);
    cudaGetSymbolAddress((void**)&gt1, g_t1);
    cudaGetSymbolAddress((void**)&gz1, g_z1);
    cudaGetSymbolAddress((void**)&gt2, g_t2);

    cudaFuncSetAttribute(gemm_k<true>,  cudaFuncAttributeMaxDynamicSharedMemorySize, GEMM_SMEM_BYTES);
    cudaFuncSetAttribute(gemm_k<false>, cudaFuncAttributeMaxDynamicSharedMemorySize, GEMM_SMEM_BYTES);
    cudaFuncSetAttribute(attn4, cudaFuncAttributeMaxDynamicSharedMemorySize, ATT_SMEM_BYTES);

    // fused QKV projections + per-head l2norm epilogue
    gemm_k<true><<<dim3(8, 64), 256, GEMM_SMEM_BYTES>>>(x, Wq, Wk, Wv, nullptr,
                                                        gq, gk, gv, 0, 512, 0);

    // fused attention (128x64 tiles, 2 CTAs/SM)
    attn4<<<dim3(HH, SS / 128, BB), 256, ATT_SMEM_BYTES>>>(gq, gk, gv, dist, omega, gy);

    // output projection + LN1
    gemm_k<false><<<dim3(4, 64), 256, GEMM_SMEM_BYTES>>>(gy, Wo, nullptr, nullptr, bo,
                                                         gt1, nullptr, nullptr, 512, 512, 0);
    add_ln_kernel<<<NTOK, 128>>>(x, gt1, l1w, l1b, gz1);

    // FFN + leaky relu + LN2
    gemm_k<false><<<dim3(4, 64), 256, GEMM_SMEM_BYTES>>>(gz1, Wf, nullptr, nullptr, bf,
                                                         gt2, nullptr, nullptr, 512, 512, 1);
    add_ln_kernel<<<NTOK, 128>>>(gz1, gt2, l2w, l2b, out);
}

// round 8
// speedup vs baseline: 3.6989x; 1.0993x over previous
#include <cuda_runtime.h>
#include <math.h>

#define BB 8
#define SS 1024
#define HH 8
#define NTOK 8192

// ---------------- device scratch ----------------
__device__ float g_q [NTOK*256];   // [token][h*32+k], l2-normalized
__device__ float g_k [NTOK*256];
__device__ float g_v [NTOK*512];   // TRANSPOSED: [b][h][c(64)][s(1024)]
__device__ float g_y [NTOK*512];
__device__ float g_t1[NTOK*512];
__device__ float g_z1[NTOK*512];
__device__ float g_t2[NTOK*512];

// ---------------- primitives ----------------
__device__ __forceinline__ void mma8(float* c, const unsigned* a, const unsigned* b) {
    asm volatile(
        "mma.sync.aligned.m16n8k8.row.col.f32.tf32.tf32.f32 "
        "{%0,%1,%2,%3},{%4,%5,%6,%7},{%8,%9},{%0,%1,%2,%3};"
        : "+f"(c[0]), "+f"(c[1]), "+f"(c[2]), "+f"(c[3])
        : "r"(a[0]), "r"(a[1]), "r"(a[2]), "r"(a[3]), "r"(b[0]), "r"(b[1]));
}
// x4 b16 ldmatrix on tf32 data: lane l addresses row (R + (l&15)), k-col (K + (l>>4)*4).
__device__ __forceinline__ void ldsm4(unsigned* r, unsigned addr) {
    asm volatile("ldmatrix.sync.aligned.m8n8.x4.shared.b16 {%0,%1,%2,%3}, [%4];"
        : "=r"(r[0]), "=r"(r[1]), "=r"(r[2]), "=r"(r[3]) : "r"(addr));
}
__device__ __forceinline__ void cpa16(unsigned dst, const void* src) {
    asm volatile("cp.async.cg.shared.global [%0], [%1], 16;\n" :: "r"(dst), "l"(src));
}
#define CP_COMMIT asm volatile("cp.async.commit_group;\n" ::: "memory")
#define CP_WAIT0  asm volatile("cp.async.wait_group 0;\n" ::: "memory")
#define CP_WAIT1  asm volatile("cp.async.wait_group 1;\n" ::: "memory")

// ---------------- GEMM: C[M,N] = A[M,K] * W[N,K]^T, 3-stage pipeline ----------------
#define GST 36
#define GSTG (128*GST)
#define GSTAGE (2*GSTG)
#define GEMM_SMEM_BYTES (3*GSTAGE*4)   /* 110592 */

template<bool QKV>
__global__ __launch_bounds__(256, 2) void gemm_k(
    const float* __restrict__ A, const float* __restrict__ W0,
    const float* __restrict__ W1, const float* __restrict__ W2,
    const float* __restrict__ bias,
    float* __restrict__ C0, float* __restrict__ C1, float* __restrict__ C2,
    int Ngen, int K, int act)
{
    extern __shared__ unsigned gsm[];   // [3 stages][A 128x36 | W 128x36]

    const int tid = threadIdx.x, warp = tid >> 5, lane = tid & 31;
    const int g = lane >> 2, c = lane & 3;
    const int lrow = lane & 15, lk4 = (lane >> 4) << 2;
    const int warpM = (warp >> 1) * 32, warpN = (warp & 1) * 64;
    const int m0 = blockIdx.y * 128, bx = blockIdx.x;

    const float* W; float* C; int Nout, col0; bool norm = false, vmode = false;
    if (QKV) {
        if (bx < 2)      { W = W0; C = C0; Nout = 256; col0 = bx * 128;       norm = true; }
        else if (bx < 4) { W = W1; C = C1; Nout = 256; col0 = (bx - 2) * 128; norm = true; }
        else             { W = W2; C = C2; Nout = 512; col0 = (bx - 4) * 128; vmode = true; }
    } else { W = W0; C = C0; Nout = Ngen; col0 = bx * 128; }

    const unsigned sB = (unsigned)__cvta_generic_to_shared(gsm);

    auto pre = [&](int kc, int st) {
        const int k0 = kc * 32;
        const unsigned base = sB + (unsigned)(st * GSTAGE) * 4;
#pragma unroll
        for (int i = 0; i < 4; i++) {
            int slot = tid + i * 256;
            int row = slot >> 3, ch = (slot & 7) * 4;
            cpa16(base + (unsigned)(row * GST + ch) * 4,
                  A + (size_t)(m0 + row) * K + k0 + ch);
            cpa16(base + (unsigned)(GSTG + row * GST + ch) * 4,
                  W + (size_t)(col0 + row) * K + k0 + ch);
        }
    };

    float acc[2][8][4];
#pragma unroll
    for (int mi = 0; mi < 2; mi++)
#pragma unroll
        for (int ni = 0; ni < 8; ni++)
#pragma unroll
            for (int j = 0; j < 4; j++) acc[mi][ni][j] = 0.f;

    const int NC = K / 32;
    pre(0, 0); CP_COMMIT;
    pre(1, 1); CP_COMMIT;
    int st = 0;
    for (int kc = 0; kc < NC; kc++) {
        CP_WAIT1;
        __syncthreads();
        if (kc + 2 < NC) pre(kc + 2, (st + 2) % 3);
        CP_COMMIT;
        const unsigned abase = sB + (unsigned)(st * GSTAGE) * 4;
        const unsigned wbase = abase + (unsigned)GSTG * 4;
#pragma unroll
        for (int kk = 0; kk < 32; kk += 8) {
            unsigned af[2][4];
#pragma unroll
            for (int mi = 0; mi < 2; mi++)
                ldsm4(af[mi], abase + (unsigned)((warpM + mi * 16 + lrow) * GST + kk + lk4) * 4);
            unsigned bq[4][4];
#pragma unroll
            for (int p = 0; p < 4; p++)
                ldsm4(bq[p], wbase + (unsigned)((warpN + p * 16 + lrow) * GST + kk + lk4) * 4);
#pragma unroll
            for (int ni = 0; ni < 8; ni++) {
                unsigned bf[2] = { bq[ni >> 1][ni & 1], bq[ni >> 1][2 + (ni & 1)] };
#pragma unroll
                for (int mi = 0; mi < 2; mi++) mma8(acc[mi][ni], af[mi], bf);
            }
        }
        st = (st + 1) % 3;
    }

#pragma unroll
    for (int mi = 0; mi < 2; mi++) {
        float r0A = 1.f, r0B = 1.f, r1A = 1.f, r1B = 1.f;
        if (QKV && norm) {
            float a0 = 0.f, a1 = 0.f, b0 = 0.f, b1 = 0.f;
#pragma unroll
            for (int ni = 0; ni < 4; ni++) {
                a0 += acc[mi][ni][0]*acc[mi][ni][0] + acc[mi][ni][1]*acc[mi][ni][1];
                a1 += acc[mi][ni][2]*acc[mi][ni][2] + acc[mi][ni][3]*acc[mi][ni][3];
            }
#pragma unroll
            for (int ni = 4; ni < 8; ni++) {
                b0 += acc[mi][ni][0]*acc[mi][ni][0] + acc[mi][ni][1]*acc[mi][ni][1];
                b1 += acc[mi][ni][2]*acc[mi][ni][2] + acc[mi][ni][3]*acc[mi][ni][3];
            }
            a0 += __shfl_xor_sync(0xffffffffu, a0, 1); a0 += __shfl_xor_sync(0xffffffffu, a0, 2);
            a1 += __shfl_xor_sync(0xffffffffu, a1, 1); a1 += __shfl_xor_sync(0xffffffffu, a1, 2);
            b0 += __shfl_xor_sync(0xffffffffu, b0, 1); b0 += __shfl_xor_sync(0xffffffffu, b0, 2);
            b1 += __shfl_xor_sync(0xffffffffu, b1, 1); b1 += __shfl_xor_sync(0xffffffffu, b1, 2);
            r0A = 1.f / fmaxf(sqrtf(a0), 1e-12f);
            r1A = 1.f / fmaxf(sqrtf(a1), 1e-12f);
            r0B = 1.f / fmaxf(sqrtf(b0), 1e-12f);
            r1B = 1.f / fmaxf(sqrtf(b1), 1e-12f);
        }
        const int row0 = m0 + warpM + mi * 16 + g;
#pragma unroll
        for (int ni = 0; ni < 8; ni++) {
            const int col = col0 + warpN + ni * 8 + 2 * c;
            float o0 = acc[mi][ni][0], o1 = acc[mi][ni][1];
            float o2 = acc[mi][ni][2], o3 = acc[mi][ni][3];
            if (QKV) {
                if (norm) {
                    float ra = (ni < 4) ? r0A : r0B;
                    float rb = (ni < 4) ? r1A : r1B;
                    o0 *= ra; o1 *= ra; o2 *= rb; o3 *= rb;
                }
            } else {
                float bx_ = bias[col], by_ = bias[col + 1];
                o0 += bx_; o1 += by_; o2 += bx_; o3 += by_;
                if (act) {
                    o0 = o0 > 0.f ? o0 : 0.01f * o0;
                    o1 = o1 > 0.f ? o1 : 0.01f * o1;
                    o2 = o2 > 0.f ? o2 : 0.01f * o2;
                    o3 = o3 > 0.f ? o3 : 0.01f * o3;
                }
            }
            if (QKV && vmode) {
                // transposed V store: [b][h][c][s]; tok = row0 / row0+8
                int h = col >> 6, cc = col & 63;
                int bidx = row0 >> 10, s = row0 & 1023;
                float* vt = C + ((size_t)(bidx * 8 + h) * 64 + cc) * 1024 + s;
                vt[0]        = o0;   // (cc,   tok)
                vt[1024]     = o1;   // (cc+1, tok)
                vt[8]        = o2;   // (cc,   tok+8)
                vt[1024 + 8] = o3;
            } else {
                *(float2*)&C[(size_t)row0 * Nout + col]       = make_float2(o0, o1);
                *(float2*)&C[(size_t)(row0 + 8) * Nout + col] = make_float2(o2, o3);
            }
        }
    }
}

// ---------------- fused attention: CTA 128(q) x 64(t), 2 CTAs/SM ----------------
#define KST 36
#define VST 68
#define ZST 68
#define ATT_WORDS (128*KST + 2*64*KST + 2*64*VST + 128*ZST + 128)
#define ATT_SMEM_BYTES (ATT_WORDS*4)   /* 107008 */

__global__ __launch_bounds__(256, 2) void attn5(
    const float* __restrict__ qn, const float* __restrict__ kn,
    const float* __restrict__ vt, const float* __restrict__ dist,
    const float* __restrict__ omega, float* __restrict__ yout)
{
    extern __shared__ unsigned sm[];
    unsigned* qs  = sm;                         // [128][36]
    unsigned* ks  = qs + 128*KST;               // [2][64][36]
    unsigned* vsT = ks + 2*64*KST;              // [2][64 c][68 t]  (V transposed)
    float*    zs  = (float*)(vsT + 2*64*VST);   // [128][68]
    float*    rs  = zs + 128*ZST;               // [128]

    const int h = blockIdx.x, b = blockIdx.y;
    const int qi = (int)(gridDim.z - 1 - blockIdx.z);   // global heavy-first
    const int q0 = qi * 128;
    const int tid = threadIdx.x, warp = tid >> 5, lane = tid & 31;
    const int g = lane >> 2, c = lane & 3;
    const int lrow = lane & 15, lk4 = (lane >> 4) << 2;
    const int warpM = (warp >> 1) * 32, warpN = (warp & 1) * 32;
    const float om = omega[h];
    if (tid < 128) rs[tid] = 0.f;

    const unsigned sq = (unsigned)__cvta_generic_to_shared(qs);
    const unsigned sk = (unsigned)__cvta_generic_to_shared(ks);
    const unsigned sv = (unsigned)__cvta_generic_to_shared(vsT);
    const unsigned sz = (unsigned)__cvta_generic_to_shared(zs);

    const float* vbase = vt + (size_t)(b * 8 + h) * 64 * 1024;

    auto ldK = [&](int st, int t0) {
#pragma unroll
        for (int i = 0; i < 2; i++) {
            int slot = tid + i * 256, row = slot >> 3, ch = (slot & 7) * 4;
            cpa16(sk + (unsigned)(st * 64 * KST + row * KST + ch) * 4,
                  kn + (size_t)(b * SS + t0 + row) * 256 + h * 32 + ch);
        }
    };
    auto ldV = [&](int st, int t0) {   // V^T tile: 64 c-rows x 64 t
#pragma unroll
        for (int i = 0; i < 4; i++) {
            int slot = tid + i * 256, row = slot >> 4, ch = (slot & 15) * 4;
            cpa16(sv + (unsigned)(st * 64 * VST + row * VST + ch) * 4,
                  vbase + (size_t)row * 1024 + t0 + ch);
        }
    };
    // Q tile (128 x 32)
#pragma unroll
    for (int i = 0; i < 4; i++) {
        int slot = tid + i * 256, row = slot >> 3, ch = (slot & 7) * 4;
        cpa16(sq + (unsigned)(row * KST + ch) * 4,
              qn + (size_t)(b * SS + q0 + row) * 256 + h * 32 + ch);
    }
    ldK(0, 0); ldV(0, 0); CP_COMMIT;

    float oacc[2][4][4];
#pragma unroll
    for (int mi = 0; mi < 2; mi++)
#pragma unroll
        for (int ni = 0; ni < 4; ni++)
#pragma unroll
            for (int j = 0; j < 4; j++) oacc[mi][ni][j] = 0.f;
    float rsacc[2][2] = {{0.f, 0.f}, {0.f, 0.f}};

    const int nkt = 2 * qi + 2;
    int st = 0;
    for (int kt = 0; kt < nkt; kt++) {
        const int t0 = kt * 64;
        CP_WAIT0;
        __syncthreads();
        if (kt + 1 < nkt) { ldK(st ^ 1, t0 + 64); ldV(st ^ 1, t0 + 64); }
        CP_COMMIT;

        const unsigned kof = st * 64 * KST, vof = st * 64 * VST;

        // ---- S = Q K^T ----
        float sfr[2][4][4];
#pragma unroll
        for (int mi = 0; mi < 2; mi++)
#pragma unroll
            for (int ni = 0; ni < 4; ni++)
#pragma unroll
                for (int j = 0; j < 4; j++) sfr[mi][ni][j] = 0.f;
#pragma unroll
        for (int kk = 0; kk < 4; kk++) {
            unsigned af[2][4];
#pragma unroll
            for (int mi = 0; mi < 2; mi++)
                ldsm4(af[mi], sq + (unsigned)((warpM + mi * 16 + lrow) * KST + kk * 8 + lk4) * 4);
            unsigned bq[2][4];
#pragma unroll
            for (int p = 0; p < 2; p++)
                ldsm4(bq[p], sk + (unsigned)(kof + (warpN + p * 16 + lrow) * KST + kk * 8 + lk4) * 4);
#pragma unroll
            for (int ni = 0; ni < 4; ni++) {
                unsigned bf[2] = { bq[ni >> 1][ni & 1], bq[ni >> 1][2 + (ni & 1)] };
#pragma unroll
                for (int mi = 0; mi < 2; mi++) mma8(sfr[mi][ni], af[mi], bf);
            }
        }

        // ---- bias + exp + mask; z -> smem; partial row sums ----
        const bool needmask = (kt >= 2 * qi);
#pragma unroll
        for (int mi = 0; mi < 2; mi++) {
            const int rl0 = warpM + mi * 16 + g;
            const int qrow0 = q0 + rl0, qrow1 = qrow0 + 8;
#pragma unroll
            for (int ni = 0; ni < 4; ni++) {
                const int tcl = warpN + ni * 8 + 2 * c;
                const int tc0 = t0 + tcl;
                float2 d0 = __ldg((const float2*)(dist + (size_t)(b * SS + qrow0) * SS + tc0));
                float2 d1 = __ldg((const float2*)(dist + (size_t)(b * SS + qrow1) * SS + tc0));
                float z00 = __expf(sfr[mi][ni][0] + __expf(-om * d0.x) - 1.f);
                float z01 = __expf(sfr[mi][ni][1] + __expf(-om * d0.y) - 1.f);
                float z10 = __expf(sfr[mi][ni][2] + __expf(-om * d1.x) - 1.f);
                float z11 = __expf(sfr[mi][ni][3] + __expf(-om * d1.y) - 1.f);
                if (needmask) {
                    if (tc0     > qrow0) z00 = 0.f;
                    if (tc0 + 1 > qrow0) z01 = 0.f;
                    if (tc0     > qrow1) z10 = 0.f;
                    if (tc0 + 1 > qrow1) z11 = 0.f;
                }
                rsacc[mi][0] += z00 + z01;
                rsacc[mi][1] += z10 + z11;
                *(float2*)(zs + rl0 * ZST + tcl)       = make_float2(z00, z01);
                *(float2*)(zs + (rl0 + 8) * ZST + tcl) = make_float2(z10, z11);
            }
        }
        __syncthreads();

        // ---- O += Z V  (both operands via ldmatrix) ----
#pragma unroll
        for (int kk = 0; kk < 8; kk++) {
            unsigned zf[2][4];
#pragma unroll
            for (int mi = 0; mi < 2; mi++)
                ldsm4(zf[mi], sz + (unsigned)((warpM + mi * 16 + lrow) * ZST + kk * 8 + lk4) * 4);
            unsigned bq[2][4];
#pragma unroll
            for (int p = 0; p < 2; p++)
                ldsm4(bq[p], sv + (unsigned)(vof + (warpN + p * 16 + lrow) * VST + kk * 8 + lk4) * 4);
#pragma unroll
            for (int ni = 0; ni < 4; ni++) {
                unsigned bf[2] = { bq[ni >> 1][ni & 1], bq[ni >> 1][2 + (ni & 1)] };
#pragma unroll
                for (int mi = 0; mi < 2; mi++) mma8(oacc[mi][ni], zf[mi], bf);
            }
        }
        st ^= 1;
    }

    // ---- one-time row-sum reduction ----
#pragma unroll
    for (int mi = 0; mi < 2; mi++) {
#pragma unroll
        for (int r = 0; r < 2; r++) {
            rsacc[mi][r] += __shfl_xor_sync(0xffffffffu, rsacc[mi][r], 1);
            rsacc[mi][r] += __shfl_xor_sync(0xffffffffu, rsacc[mi][r], 2);
        }
        if (c == 0) {
            atomicAdd(&rs[warpM + mi * 16 + g], rsacc[mi][0]);
            atomicAdd(&rs[warpM + mi * 16 + g + 8], rsacc[mi][1]);
        }
    }
    __syncthreads();

    // ---- normalize by (rowsum + 1), write concat layout ----
#pragma unroll
    for (int mi = 0; mi < 2; mi++) {
        const int rl0 = warpM + mi * 16 + g;
        const float inv0 = 1.f / (rs[rl0] + 1.f);
        const float inv1 = 1.f / (rs[rl0 + 8] + 1.f);
#pragma unroll
        for (int ni = 0; ni < 4; ni++) {
            int col = h * 64 + warpN + ni * 8 + 2 * c;
            *(float2*)(yout + (size_t)(b * SS + q0 + rl0) * 512 + col) =
                make_float2(oacc[mi][ni][0] * inv0, oacc[mi][ni][1] * inv0);
            *(float2*)(yout + (size_t)(b * SS + q0 + rl0 + 8) * 512 + col) =
                make_float2(oacc[mi][ni][2] * inv1, oacc[mi][ni][3] * inv1);
        }
    }
}

// ---------------- residual add + LayerNorm over 512 ----------------
__global__ __launch_bounds__(128) void add_ln_kernel(
    const float* __restrict__ A, const float* __restrict__ Bs,
    const float* __restrict__ w, const float* __restrict__ bias,
    float* __restrict__ out)
{
    const int row = blockIdx.x;
    const int t = threadIdx.x;
    __shared__ float red[8];

    float4 a4 = *(const float4*)(A  + (size_t)row * 512 + t * 4);
    float4 b4 = *(const float4*)(Bs + (size_t)row * 512 + t * 4);
    float v0 = a4.x + b4.x, v1 = a4.y + b4.y, v2 = a4.z + b4.z, v3 = a4.w + b4.w;

    float s = v0 + v1 + v2 + v3;
#pragma unroll
    for (int o = 16; o > 0; o >>= 1) s += __shfl_xor_sync(0xffffffffu, s, o);
    int wid = t >> 5, lane = t & 31;
    if (!lane) red[wid] = s;
    __syncthreads();
    float mean = (red[0] + red[1] + red[2] + red[3]) * (1.f / 512.f);

    float d0 = v0 - mean, d1 = v1 - mean, d2 = v2 - mean, d3 = v3 - mean;
    float sv = d0*d0 + d1*d1 + d2*d2 + d3*d3;
#pragma unroll
    for (int o = 16; o > 0; o >>= 1) sv += __shfl_xor_sync(0xffffffffu, sv, o);
    if (!lane) red[4 + wid] = sv;
    __syncthreads();
    float var = (red[4] + red[5] + red[6] + red[7]) * (1.f / 512.f);
    float rstd = rsqrtf(var + 1e-5f);

    float4 w4  = *(const float4*)(w    + t * 4);
    float4 bb4 = *(const float4*)(bias + t * 4);
    float4 o4;
    o4.x = d0 * rstd * w4.x + bb4.x;
    o4.y = d1 * rstd * w4.y + bb4.y;
    o4.z = d2 * rstd * w4.z + bb4.z;
    o4.w = d3 * rstd * w4.w + bb4.w;
    *(float4*)(out + (size_t)row * 512 + t * 4) = o4;
}

// ---------------- launch ----------------
extern "C" void kernel_launch(void* const* d_in, const int* in_sizes, int n_in,
                              void* d_out, int out_size)
{
    const float* x     = (const float*)d_in[0];
    const float* dist  = (const float*)d_in[2];
    const float* Wq    = (const float*)d_in[3];
    const float* Wk    = (const float*)d_in[4];
    const float* Wv    = (const float*)d_in[5];
    const float* omega = (const float*)d_in[6];
    const float* Wo    = (const float*)d_in[7];
    const float* bo    = (const float*)d_in[8];
    const float* Wf    = (const float*)d_in[9];
    const float* bf    = (const float*)d_in[10];
    const float* l1w   = (const float*)d_in[11];
    const float* l1b   = (const float*)d_in[12];
    const float* l2w   = (const float*)d_in[13];
    const float* l2b   = (const float*)d_in[14];
    float* out = (float*)d_out;

    float *gq, *gk, *gv, *gy, *gt1, *gz1, *gt2;
    cudaGetSymbolAddress((void**)&gq,  g_q);
    cudaGetSymbolAddress((void**)&gk,  g_k);
    cudaGetSymbolAddress((void**)&gv,  g_v);
    cudaGetSymbolAddress((void**)&gy,  g_y);
    cudaGetSymbolAddress((void**)&gt1, g_t1);
    cudaGetSymbolAddress((void**)&gz1, g_z1);
    cudaGetSymbolAddress((void**)&gt2, g_t2);

    cudaFuncSetAttribute(gemm_k<true>,  cudaFuncAttributeMaxDynamicSharedMemorySize, GEMM_SMEM_BYTES);
    cudaFuncSetAttribute(gemm_k<false>, cudaFuncAttributeMaxDynamicSharedMemorySize, GEMM_SMEM_BYTES);
    cudaFuncSetAttribute(attn5, cudaFuncAttributeMaxDynamicSharedMemorySize, ATT_SMEM_BYTES);

    // fused QKV projections + per-head l2norm; V written transposed
    gemm_k<true><<<dim3(8, 64), 256, GEMM_SMEM_BYTES>>>(x, Wq, Wk, Wv, nullptr,
                                                        gq, gk, gv, 0, 512, 0);

    // fused attention (128x64 tiles, 2 CTAs/SM, heavy CTAs globally first)
    attn5<<<dim3(HH, BB, SS / 128), 256, ATT_SMEM_BYTES>>>(gq, gk, gv, dist, omega, gy);

    // output projection + LN1
    gemm_k<false><<<dim3(4, 64), 256, GEMM_SMEM_BYTES>>>(gy, Wo, nullptr, nullptr, bo,
                                                         gt1, nullptr, nullptr, 512, 512, 0);
    add_ln_kernel<<<NTOK, 128>>>(x, gt1, l1w, l1b, gz1);

    // FFN + leaky relu + LN2
    gemm_k<false><<<dim3(4, 64), 256, GEMM_SMEM_BYTES>>>(gz1, Wf, nullptr, nullptr, bf,
                                                         gt2, nullptr, nullptr, 512, 512, 1);
    add_ln_kernel<<<NTOK, 128>>>(gz1, gt2, l2w, l2b, out);
}